// round 11
// baseline (speedup 1.0000x reference)
#include <cuda_runtime.h>
#include <cuda_bf16.h>
#include <math.h>
#include <stdint.h>

#define NB   8
#define NT   12
#define BTT  96
#define NN   10000
#define NH   64
#define NC   2
#define NE   320000
#define ROWS (BTT*NN)    // 960000

// ======================= mma.sync helpers ===================================
__device__ __forceinline__ uint32_t smem_to_u32(const void* p) {
    uint32_t a;
    asm("{ .reg .u64 t; cvta.to.shared.u64 t, %1; cvt.u32.u64 %0, t; }" : "=r"(a) : "l"(p));
    return a;
}
__device__ __forceinline__ void ldsm4(uint32_t* r, uint32_t addr) {
    asm volatile("ldmatrix.sync.aligned.m8n8.x4.shared.b16 {%0,%1,%2,%3}, [%4];"
        : "=r"(r[0]), "=r"(r[1]), "=r"(r[2]), "=r"(r[3]) : "r"(addr));
}
__device__ __forceinline__ void ldsm2(uint32_t* r, uint32_t addr) {
    asm volatile("ldmatrix.sync.aligned.m8n8.x2.shared.b16 {%0,%1}, [%2];"
        : "=r"(r[0]), "=r"(r[1]) : "r"(addr));
}
__device__ __forceinline__ void mma16816(float* c, const uint32_t* a, const uint32_t* b) {
    asm volatile(
        "mma.sync.aligned.m16n8k16.row.col.f32.bf16.bf16.f32 "
        "{%0,%1,%2,%3}, {%4,%5,%6,%7}, {%8,%9}, {%0,%1,%2,%3};"
        : "+f"(c[0]), "+f"(c[1]), "+f"(c[2]), "+f"(c[3])
        : "r"(a[0]), "r"(a[1]), "r"(a[2]), "r"(a[3]), "r"(b[0]), "r"(b[1]));
}
__device__ __forceinline__ uint32_t packbf(float x0, float x1) {
    uint32_t r;
    asm("cvt.rn.bf16x2.f32 %0, %1, %2;" : "=r"(r) : "f"(x1), "f"(x0));
    return r;
}
__device__ __forceinline__ void split_pair(float x0, float x1, uint32_t& hi, uint32_t& lo) {
    hi = packbf(x0, x1);
    float h0 = __bfloat162float(__float2bfloat16(x0));
    float h1 = __bfloat162float(__float2bfloat16(x1));
    lo = packbf(x0 - h0, x1 - h1);
}

// ======================= scratch ============================================
__device__ float g_T0 [ROWS*NH];
__device__ float g_Tx1[ROWS*NH];
__device__ float g_cheb[ROWS*NH];

__device__ float g_deg[NN];
__device__ float g_dis[NN];
__device__ int   g_cnt[NN];
__device__ int   g_off[NN+1];
__device__ int   g_cur[NN];
__device__ int   g_csr_col[NE];
__device__ float g_csr_w[NE];
__device__ float g_Wcat[192*64];
__device__ uint32_t g_WcatH[6912];   // bf16x2 hi words, smem layout order
__device__ uint32_t g_WcatL[6912];   // bf16x2 lo words
__device__ float g_Wtc2[3*192*64];

// ======================= graph preprocessing ================================
__global__ void zero_kernel() {
    int i = blockIdx.x*256 + threadIdx.x;
    if (i < NN) { g_deg[i] = 0.f; g_cnt[i] = 0; g_cur[i] = 0; }
}
__global__ void degcnt_kernel(const int* __restrict__ ei, const float* __restrict__ ew) {
    int e = blockIdx.x*256 + threadIdx.x;
    if (e < NE) {
        int r = ei[e];
        atomicAdd(&g_deg[r], ew[e]);
        atomicAdd(&g_cnt[r], 1);
    }
}
__global__ void dis_kernel() {
    int i = blockIdx.x*256 + threadIdx.x;
    if (i < NN) {
        float d = g_deg[i];
        g_dis[i] = d > 0.f ? rsqrtf(d) : 0.f;
    }
}
__global__ void scan_kernel() {
    __shared__ int sums[1024];
    int tid = threadIdx.x;
    const int CH = (NN + 1023) / 1024;
    int base = tid * CH;
    int s = 0;
    for (int i = 0; i < CH; i++) { int idx = base + i; if (idx < NN) s += g_cnt[idx]; }
    sums[tid] = s;
    __syncthreads();
    for (int d = 1; d < 1024; d <<= 1) {
        int v = (tid >= d) ? sums[tid - d] : 0;
        __syncthreads();
        sums[tid] += v;
        __syncthreads();
    }
    int run = sums[tid] - s;
    for (int i = 0; i < CH; i++) {
        int idx = base + i;
        if (idx < NN) { g_off[idx] = run; run += g_cnt[idx]; }
    }
    if (tid == 1023) g_off[NN] = sums[1023];
}
__global__ void scatter_kernel(const int* __restrict__ ei, const float* __restrict__ ew) {
    int e = blockIdx.x*256 + threadIdx.x;
    if (e < NE) {
        int r = ei[e];
        int c = ei[NE + e];
        int pos = g_off[r] + atomicAdd(&g_cur[r], 1);
        g_csr_col[pos] = c;
        g_csr_w[pos]   = -g_dis[r] * ew[e] * g_dis[c];
    }
}

// ======================= weight repacking ===================================
__global__ void wcat_kernel(const float* __restrict__ W) {
    int idx = blockIdx.x*256 + threadIdx.x;
    if (idx >= 192*64) return;
    int k = idx >> 6, j = idx & 63;
    float v;
    if (k < 64)       v = W[k*64 + j] - W[2*4096 + k*64 + j];
    else if (k < 128) v = W[4096 + (k-64)*64 + j];
    else              v = 2.f * W[2*4096 + (k-128)*64 + j];
    g_Wcat[idx] = v;
}
// split Wcat into bf16 hi/lo words, laid out exactly as the GEMM B smem
__global__ void wsplit_kernel() {
    int p = blockIdx.x*256 + threadIdx.x;
    if (p >= 6144) return;
    int n = p / 96;
    int kp = (p - n*96) * 2;
    int chunk = kp >> 6, kin = kp & 63;
    float w0 = g_Wcat[kp*64 + n];
    float w1 = g_Wcat[(kp+1)*64 + n];
    uint32_t hi, lo;
    split_pair(w0, w1, hi, lo);
    int word = (chunk*64 + n)*36 + (kin >> 1);
    g_WcatH[word] = hi;
    g_WcatL[word] = lo;
}
__global__ void wtc2_kernel(const float* __restrict__ w1,
                            const float* __restrict__ w2,
                            const float* __restrict__ w3) {
    int idx = blockIdx.x*256 + threadIdx.x;
    if (idx >= 3*192*64) return;
    int j = idx / 12288;
    int r = idx - j*12288;
    int k = r >> 6, h = r & 63;
    int dt = k >> 6;
    int c  = k & 63;
    const float* w = (j == 0) ? w1 : (j == 1) ? w2 : w3;
    g_Wtc2[idx] = w[h*192 + c*3 + dt];
}

// ======================= TC1 ================================================
__global__ void tc1_kernel(const float* __restrict__ X,
                           const float* __restrict__ w1, const float* __restrict__ b1,
                           const float* __restrict__ w2, const float* __restrict__ b2,
                           const float* __restrict__ w3, const float* __restrict__ b3) {
    __shared__ float s1[384], s2[384], s3[384];
    __shared__ float sb[3][64];
    __shared__ float sx[4][8];
    int tid = threadIdx.x;
    for (int i = tid; i < 384; i += 256) { s1[i] = w1[i]; s2[i] = w2[i]; s3[i] = w3[i]; }
    if (tid < 64) { sb[0][tid] = b1[tid]; sb[1][tid] = b2[tid]; sb[2][tid] = b3[tid]; }
    int bt = blockIdx.y;
    int b = bt / NT, t = bt - b*NT;
    int n0 = blockIdx.x * 4;
    if (tid < 24) {
        int nl = tid / 6, idx = tid % 6;
        int k = idx >> 1, c = idx & 1;
        int tt = t + k - 1;
        float v = 0.f;
        if (tt >= 0 && tt < NT) v = X[(((b*NT + tt)*NN) + (n0 + nl))*NC + c];
        sx[nl][k*2 + c] = v;
    }
    __syncthreads();
    int h = tid & 63, nl = tid >> 6;
    float p = sb[0][h], q = sb[1][h], r = sb[2][h];
    #pragma unroll
    for (int k = 0; k < 3; k++)
        #pragma unroll
        for (int c = 0; c < 2; c++) {
            float xv = sx[nl][k*2 + c];
            int wi = h*6 + c*3 + k;
            p += s1[wi]*xv; q += s2[wi]*xv; r += s3[wi]*xv;
        }
    float sg = 1.f / (1.f + expf(-q));
    float o  = p*sg + r;
    g_T0[(bt*NN + n0 + nl)*NH + h] = fmaxf(o, 0.f);
}

// ======================= prop1: Tx1 = L T0 ==================================
__global__ void prop1_kernel() {
    int n    = blockIdx.x;
    int warp = threadIdx.x >> 5, lane = threadIdx.x & 31;
    int bt   = blockIdx.y*8 + warp*2 + (lane >> 4);
    int hq   = lane & 15;
    int e0 = g_off[n], e1 = g_off[n+1];
    const float4* xs = (const float4*)g_T0;
    float4 acc0 = make_float4(0.f, 0.f, 0.f, 0.f);
    float4 acc1 = make_float4(0.f, 0.f, 0.f, 0.f);
    int base = bt * NN;
    int e = e0;
    for (; e + 1 < e1; e += 2) {
        int   c0 = g_csr_col[e],   c1 = g_csr_col[e+1];
        float w0 = g_csr_w[e],     w1 = g_csr_w[e+1];
        float4 v0 = __ldg(&xs[(base + c0)*16 + hq]);
        float4 v1 = __ldg(&xs[(base + c1)*16 + hq]);
        acc0.x += w0*v0.x; acc0.y += w0*v0.y; acc0.z += w0*v0.z; acc0.w += w0*v0.w;
        acc1.x += w1*v1.x; acc1.y += w1*v1.y; acc1.z += w1*v1.z; acc1.w += w1*v1.w;
    }
    if (e < e1) {
        int   c = g_csr_col[e];
        float w = g_csr_w[e];
        float4 v = __ldg(&xs[(base + c)*16 + hq]);
        acc0.x += w*v.x; acc0.y += w*v.y; acc0.z += w*v.z; acc0.w += w*v.w;
    }
    acc0.x += acc1.x; acc0.y += acc1.y; acc0.z += acc1.z; acc0.w += acc1.w;
    ((float4*)g_Tx1)[(base + n)*16 + hq] = acc0;
}

// ======================= fused prop2 + cheb GEMM ============================
// Persistent blocks. Tile = 16 nodes x 8 bt = 128 (bt,n) rows.
// Phase g: gather Tx2 = L Tx1 for the tile, split to A smem (chunk 2).
// Phase m: MMA chunks {2:Tx2, 0:T0, 1:Tx1} x Wcat(hi/lo), relu+bias -> g_cheb.
#define GC_AH   1024
#define GC_AL   19456
#define GC_BH   37888
#define GC_BL   65536
#define GC_SMEM 93184
#define GC_NT   625                // node tiles (625*16 = 10000 exactly)
#define GC_TILES (GC_NT*12)        // 12 bt-groups of 8

__device__ __forceinline__ void mma_chunk(uint32_t sbA_h, uint32_t sbB_h, int chunk,
                                          int warpM, int warpN, int lane,
                                          float acc[4][2][4]) {
    #pragma unroll
    for (int ks = 0; ks < 4; ks++) {
        int k0 = ks * 16;
        uint32_t ah[4][4], al[4][4];
        int arow = warpM*64 + ((lane>>3)&1)*8 + (lane&7);
        int acolb = (k0 + ((lane>>4)&1)*8) * 2;
        #pragma unroll
        for (int mt = 0; mt < 4; mt++) {
            uint32_t ad = sbA_h + (arow + mt*16)*144 + acolb;
            ldsm4(ah[mt], ad);
            ldsm4(al[mt], ad + (GC_AL - GC_AH));
        }
        int l4 = lane & 15;
        int bcolb = (k0 + ((l4>>3)&1)*8) * 2;
        #pragma unroll
        for (int nt = 0; nt < 2; nt++) {
            int brow = warpN*16 + (l4 & 7);
            uint32_t bh[2], bl[2];
            uint32_t bd = sbB_h + (chunk*64 + brow + nt*8)*144 + bcolb;
            ldsm2(bh, bd);
            ldsm2(bl, bd + (GC_BL - GC_BH));
            #pragma unroll
            for (int mt = 0; mt < 4; mt++) {
                mma16816(acc[mt][nt], ah[mt], bh);
                mma16816(acc[mt][nt], ah[mt], bl);
                mma16816(acc[mt][nt], al[mt], bh);
            }
        }
    }
}

__global__ __launch_bounds__(256) void prop2_gemm(const float* __restrict__ cheb_b) {
    extern __shared__ char smem[];
    uint32_t sb = smem_to_u32(smem);
    int tid = threadIdx.x, warp = tid >> 5, lane = tid & 31;
    int warpM = warp >> 2, warpN = warp & 3;

    if (tid < 64) ((float*)smem)[tid] = cheb_b[tid];
    for (int i = tid; i < 6912; i += 256) {
        ((uint32_t*)(smem + GC_BH))[i] = g_WcatH[i];
        ((uint32_t*)(smem + GC_BL))[i] = g_WcatL[i];
    }
    __syncthreads();

    const float* bias = (const float*)smem;
    int sub = tid >> 7;          // node within pair (gather phase)
    int r   = tid & 127;
    int btl = r >> 4;            // 0..7
    int hq  = r & 15;
    int ar  = tid >> 1;          // A row (mma staging), 0..127
    int ac0 = (tid & 1) * 32;
    int a_nl = ar >> 3, a_btl = ar & 7;
    int g = lane >> 2, tg = lane & 3;
    const float4* xs = (const float4*)g_Tx1;

    for (int tt = blockIdx.x; tt < GC_TILES; tt += gridDim.x) {
        int btg = tt / GC_NT, ntile = tt - btg*GC_NT;
        int bt0 = btg * 8;
        int n0  = ntile * 16;

        // ---- phase g: gather Tx2 tile into A smem (chunk layout) ----
        #pragma unroll 1
        for (int np = 0; np < 8; np++) {
            int nl = np*2 + sub;
            int n  = n0 + nl;
            int e0 = g_off[n], e1 = g_off[n+1];
            int base = (bt0 + btl) * NN;
            float4 acc0 = make_float4(0.f,0.f,0.f,0.f);
            float4 acc1 = make_float4(0.f,0.f,0.f,0.f);
            int e = e0;
            for (; e + 1 < e1; e += 2) {
                int   c0 = g_csr_col[e],   c1 = g_csr_col[e+1];
                float w0 = g_csr_w[e],     w1 = g_csr_w[e+1];
                float4 v0 = __ldg(&xs[(base + c0)*16 + hq]);
                float4 v1 = __ldg(&xs[(base + c1)*16 + hq]);
                acc0.x += w0*v0.x; acc0.y += w0*v0.y; acc0.z += w0*v0.z; acc0.w += w0*v0.w;
                acc1.x += w1*v1.x; acc1.y += w1*v1.y; acc1.z += w1*v1.z; acc1.w += w1*v1.w;
            }
            if (e < e1) {
                int   c = g_csr_col[e];
                float w = g_csr_w[e];
                float4 v = __ldg(&xs[(base + c)*16 + hq]);
                acc0.x += w*v.x; acc0.y += w*v.y; acc0.z += w*v.z; acc0.w += w*v.w;
            }
            acc0.x += acc1.x; acc0.y += acc1.y; acc0.z += acc1.z; acc0.w += acc1.w;
            int rl = nl*8 + btl;
            uint32_t h0, l0, h1, l1;
            split_pair(acc0.x, acc0.y, h0, l0);
            split_pair(acc0.z, acc0.w, h1, l1);
            uint32_t* dh = (uint32_t*)(smem + GC_AH + rl*144 + hq*8);
            uint32_t* dl = (uint32_t*)(smem + GC_AL + rl*144 + hq*8);
            dh[0] = h0; dh[1] = h1;
            dl[0] = l0; dl[1] = l1;
        }

        // ---- phase m ----
        size_t arow_g = ((size_t)(bt0 + a_btl)*NN + (n0 + a_nl))*64 + ac0;
        float acc[4][2][4];
        #pragma unroll
        for (int mt = 0; mt < 4; mt++)
            #pragma unroll
            for (int nt = 0; nt < 2; nt++)
                #pragma unroll
                for (int i = 0; i < 4; i++) acc[mt][nt][i] = 0.f;

        float4 pref[8];
        {
            const float4* pp = (const float4*)(g_T0 + arow_g);
            #pragma unroll
            for (int i = 0; i < 8; i++) pref[i] = pp[i];
        }
        __syncthreads();
        mma_chunk(sb + GC_AH, sb + GC_BH, 2, warpM, warpN, lane, acc);
        __syncthreads();
        // store chunk 0 (T0), prefetch chunk 1 (Tx1)
        {
            uint32_t* dh = (uint32_t*)(smem + GC_AH + ar*144 + ac0*2);
            uint32_t* dl = (uint32_t*)(smem + GC_AL + ar*144 + ac0*2);
            #pragma unroll
            for (int i = 0; i < 8; i++) {
                uint32_t h0, l0, h1, l1;
                split_pair(pref[i].x, pref[i].y, h0, l0);
                split_pair(pref[i].z, pref[i].w, h1, l1);
                dh[i*2] = h0; dh[i*2+1] = h1;
                dl[i*2] = l0; dl[i*2+1] = l1;
            }
            const float4* pp = (const float4*)(g_Tx1 + arow_g);
            #pragma unroll
            for (int i = 0; i < 8; i++) pref[i] = pp[i];
        }
        __syncthreads();
        mma_chunk(sb + GC_AH, sb + GC_BH, 0, warpM, warpN, lane, acc);
        __syncthreads();
        // store chunk 1 (Tx1)
        {
            uint32_t* dh = (uint32_t*)(smem + GC_AH + ar*144 + ac0*2);
            uint32_t* dl = (uint32_t*)(smem + GC_AL + ar*144 + ac0*2);
            #pragma unroll
            for (int i = 0; i < 8; i++) {
                uint32_t h0, l0, h1, l1;
                split_pair(pref[i].x, pref[i].y, h0, l0);
                split_pair(pref[i].z, pref[i].w, h1, l1);
                dh[i*2] = h0; dh[i*2+1] = h1;
                dl[i*2] = l0; dl[i*2+1] = l1;
            }
        }
        __syncthreads();
        mma_chunk(sb + GC_AH, sb + GC_BH, 1, warpM, warpN, lane, acc);

        // ---- epilogue: bias + relu -> g_cheb ----
        #pragma unroll
        for (int mt = 0; mt < 4; mt++) {
            int rl = warpM*64 + mt*16 + g;
            int n_a = n0 + (rl >> 3),      bt_a = bt0 + (rl & 7);
            int n_b = n0 + ((rl+8) >> 3),  bt_b = bt0 + ((rl+8) & 7);
            #pragma unroll
            for (int nt = 0; nt < 2; nt++) {
                int c = warpN*16 + nt*8 + tg*2;
                float2 v0 = make_float2(fmaxf(acc[mt][nt][0] + bias[c],   0.f),
                                        fmaxf(acc[mt][nt][1] + bias[c+1], 0.f));
                float2 v1 = make_float2(fmaxf(acc[mt][nt][2] + bias[c],   0.f),
                                        fmaxf(acc[mt][nt][3] + bias[c+1], 0.f));
                *(float2*)&g_cheb[((size_t)bt_a*NN + n_a)*64 + c] = v0;
                *(float2*)&g_cheb[((size_t)bt_b*NN + n_b)*64 + c] = v1;
            }
        }
        __syncthreads();   // protect A smem before next tile's gather writes
    }
}

// ======================= TC2: persistent mma.sync, gate-interleaved N =======
#define T2_AH   1024
#define T2_AL   19456
#define T2_BH   37888
#define T2_BL   120832
#define T2_SMEM 203776
#define NTILE_N 79
#define T2_TILES (BTT*NTILE_N)

__global__ __launch_bounds__(256) void tc2_mma(const float* __restrict__ b1,
                                               const float* __restrict__ b2,
                                               const float* __restrict__ b3,
                                               float* __restrict__ out) {
    extern __shared__ char smem[];
    uint32_t sb = smem_to_u32(smem);
    int tid = threadIdx.x, warp = tid >> 5, lane = tid & 31;
    int warpM = warp >> 2, warpN = warp & 3;

    if (tid < 64) {
        ((float*)smem)[tid]       = b1[tid];
        ((float*)smem)[64 + tid]  = b2[tid];
        ((float*)smem)[128 + tid] = b3[tid];
    }
    for (int p = tid; p < 18432; p += 256) {
        int n = p / 96;
        int kp = (p - n*96) * 2;
        int chunk = kp >> 6, kin = kp & 63;
        int gate = n >> 6, h = n & 63;
        float w0 = g_Wtc2[gate*12288 + kp*64 + h];
        float w1 = g_Wtc2[gate*12288 + (kp+1)*64 + h];
        uint32_t hi, lo;
        split_pair(w0, w1, hi, lo);
        int off = (chunk*192 + n)*144 + kin*2;
        *(uint32_t*)(smem + T2_BH + off) = hi;
        *(uint32_t*)(smem + T2_BL + off) = lo;
    }
    __syncthreads();

    const float* bP = (const float*)smem;
    const float* bQ = bP + 64;
    const float* bR = bP + 128;
    int ar = tid >> 1;
    int ac0 = (tid & 1) * 32;
    int g = lane >> 2, tg = lane & 3;

    for (int tt = blockIdx.x; tt < T2_TILES; tt += gridDim.x) {
        int bt = tt / NTILE_N, ntile = tt - bt*NTILE_N;
        int b = bt / NT, t = bt - b*NT;
        int an = ntile*128 + ar;

        float acc[4][6][4];
        #pragma unroll
        for (int mt = 0; mt < 4; mt++)
            #pragma unroll
            for (int nt = 0; nt < 6; nt++)
                #pragma unroll
                for (int i = 0; i < 4; i++) acc[mt][nt][i] = 0.f;

        const float4* pdt[3];
        #pragma unroll
        for (int dt = 0; dt < 3; dt++) {
            int ttm = t + dt - 1;
            pdt[dt] = ((an < NN) && ttm >= 0 && ttm < NT)
                    ? (const float4*)(g_cheb + ((size_t)((b*NT + ttm)*NN + an))*64 + ac0)
                    : (const float4*)0;
        }
        float4 pref[8];
        #pragma unroll
        for (int i = 0; i < 8; i++)
            pref[i] = pdt[0] ? pdt[0][i] : make_float4(0.f,0.f,0.f,0.f);

        #pragma unroll
        for (int chunk = 0; chunk < 3; chunk++) {
            uint32_t* dh = (uint32_t*)(smem + T2_AH + ar*144 + ac0*2);
            uint32_t* dl = (uint32_t*)(smem + T2_AL + ar*144 + ac0*2);
            #pragma unroll
            for (int i = 0; i < 8; i++) {
                uint32_t h0, l0, h1, l1;
                split_pair(pref[i].x, pref[i].y, h0, l0);
                split_pair(pref[i].z, pref[i].w, h1, l1);
                dh[i*2] = h0; dh[i*2+1] = h1;
                dl[i*2] = l0; dl[i*2+1] = l1;
            }
            if (chunk < 2) {
                const float4* pp = pdt[chunk+1];
                #pragma unroll
                for (int i = 0; i < 8; i++)
                    pref[i] = pp ? pp[i] : make_float4(0.f,0.f,0.f,0.f);
            }
            __syncthreads();
            #pragma unroll
            for (int ks = 0; ks < 4; ks++) {
                int k0 = ks * 16;
                uint32_t ah[4][4], al[4][4];
                int arow = warpM*64 + ((lane>>3)&1)*8 + (lane&7);
                int acolb = (k0 + ((lane>>4)&1)*8) * 2;
                #pragma unroll
                for (int mt = 0; mt < 4; mt++) {
                    uint32_t ad = sb + T2_AH + (arow + mt*16)*144 + acolb;
                    ldsm4(ah[mt], ad);
                    ldsm4(al[mt], ad + (T2_AL - T2_AH));
                }
                int l4 = lane & 15;
                int bcolb = (k0 + ((l4>>3)&1)*8) * 2;
                #pragma unroll
                for (int nt = 0; nt < 6; nt++) {
                    int gate = nt >> 1, j = nt & 1;
                    int brow = gate*64 + warpN*16 + j*8 + (l4 & 7);
                    uint32_t bh[2], bl[2];
                    uint32_t bd = sb + T2_BH + (chunk*192 + brow)*144 + bcolb;
                    ldsm2(bh, bd);
                    ldsm2(bl, bd + (T2_BL - T2_BH));
                    #pragma unroll
                    for (int mt = 0; mt < 4; mt++) {
                        mma16816(acc[mt][nt], ah[mt], bh);
                        mma16816(acc[mt][nt], ah[mt], bl);
                        mma16816(acc[mt][nt], al[mt], bh);
                    }
                }
            }
            __syncthreads();
        }
        #pragma unroll
        for (int mt = 0; mt < 4; mt++) {
            int n = ntile*128 + warpM*64 + mt*16 + g;
            #pragma unroll
            for (int j = 0; j < 2; j++) {
                int h = warpN*16 + j*8 + tg*2;
                float pb0 = bP[h], pb1 = bP[h+1];
                float qb0 = bQ[h], qb1 = bQ[h+1];
                float rb0 = bR[h], rb1 = bR[h+1];
                if (n < NN) {
                    float P0 = acc[mt][j][0] + pb0,   P1 = acc[mt][j][1] + pb1;
                    float Q0 = acc[mt][2+j][0] + qb0, Q1 = acc[mt][2+j][1] + qb1;
                    float R0 = acc[mt][4+j][0] + rb0, R1 = acc[mt][4+j][1] + rb1;
                    float s0 = 1.f / (1.f + expf(-Q0));
                    float s1 = 1.f / (1.f + expf(-Q1));
                    float2 o = make_float2(fmaxf(P0*s0 + R0, 0.f), fmaxf(P1*s1 + R1, 0.f));
                    *(float2*)&out[((size_t)bt*NN + n)*64 + h] = o;
                }
                if (n + 8 < NN) {
                    float P0 = acc[mt][j][2] + pb0,   P1 = acc[mt][j][3] + pb1;
                    float Q0 = acc[mt][2+j][2] + qb0, Q1 = acc[mt][2+j][3] + qb1;
                    float R0 = acc[mt][4+j][2] + rb0, R1 = acc[mt][4+j][3] + rb1;
                    float s0 = 1.f / (1.f + expf(-Q0));
                    float s1 = 1.f / (1.f + expf(-Q1));
                    float2 o = make_float2(fmaxf(P0*s0 + R0, 0.f), fmaxf(P1*s1 + R1, 0.f));
                    *(float2*)&out[((size_t)bt*NN + n + 8)*64 + h] = o;
                }
            }
        }
    }
}

// ======================= launcher ===========================================
extern "C" void kernel_launch(void* const* d_in, const int* in_sizes, int n_in,
                              void* d_out, int out_size) {
    const float* X     = (const float*)d_in[0];
    const int*   ei    = (const int*)  d_in[1];
    const float* ew    = (const float*)d_in[2];
    const float* t1w1  = (const float*)d_in[3];
    const float* t1b1  = (const float*)d_in[4];
    const float* t1w2  = (const float*)d_in[5];
    const float* t1b2  = (const float*)d_in[6];
    const float* t1w3  = (const float*)d_in[7];
    const float* t1b3  = (const float*)d_in[8];
    const float* chebW = (const float*)d_in[9];
    const float* chebB = (const float*)d_in[10];
    const float* t2w1  = (const float*)d_in[11];
    const float* t2b1  = (const float*)d_in[12];
    const float* t2w2  = (const float*)d_in[13];
    const float* t2b2  = (const float*)d_in[14];
    const float* t2w3  = (const float*)d_in[15];
    const float* t2b3  = (const float*)d_in[16];
    float* out = (float*)d_out;

    static int configured = 0;
    if (!configured) {
        cudaFuncSetAttribute(prop2_gemm, cudaFuncAttributeMaxDynamicSharedMemorySize, GC_SMEM);
        cudaFuncSetAttribute(tc2_mma,    cudaFuncAttributeMaxDynamicSharedMemorySize, T2_SMEM);
        configured = 1;
    }

    zero_kernel   <<<(NN + 255)/256, 256>>>();
    degcnt_kernel <<<(NE + 255)/256, 256>>>(ei, ew);
    dis_kernel    <<<(NN + 255)/256, 256>>>();
    scan_kernel   <<<1, 1024>>>();
    scatter_kernel<<<(NE + 255)/256, 256>>>(ei, ew);

    wcat_kernel  <<<(192*64 + 255)/256, 256>>>(chebW);
    wsplit_kernel<<<(6144 + 255)/256, 256>>>();
    wtc2_kernel  <<<(3*192*64 + 255)/256, 256>>>(t2w1, t2w2, t2w3);

    tc1_kernel<<<dim3(NN/4, BTT), 256>>>(X, t1w1, t1b1, t1w2, t1b2, t1w3, t1b3);

    prop1_kernel<<<dim3(NN, 12), 128>>>();

    prop2_gemm<<<296, 256, GC_SMEM>>>(chebB);

    tc2_mma<<<148, 256, T2_SMEM>>>(t2b1, t2b2, t2b3, out);
}

// round 12
// speedup vs baseline: 1.1088x; 1.1088x over previous
#include <cuda_runtime.h>
#include <cuda_bf16.h>
#include <cuda_fp16.h>
#include <math.h>
#include <stdint.h>

#define NB   8
#define NT   12
#define BTT  96
#define NN   10000
#define NH   64
#define NC   2
#define NE   320000
#define ROWS (BTT*NN)    // 960000

// ======================= mma.sync helpers ===================================
__device__ __forceinline__ uint32_t smem_to_u32(const void* p) {
    uint32_t a;
    asm("{ .reg .u64 t; cvta.to.shared.u64 t, %1; cvt.u32.u64 %0, t; }" : "=r"(a) : "l"(p));
    return a;
}
__device__ __forceinline__ void ldsm4(uint32_t* r, uint32_t addr) {
    asm volatile("ldmatrix.sync.aligned.m8n8.x4.shared.b16 {%0,%1,%2,%3}, [%4];"
        : "=r"(r[0]), "=r"(r[1]), "=r"(r[2]), "=r"(r[3]) : "r"(addr));
}
__device__ __forceinline__ void ldsm2(uint32_t* r, uint32_t addr) {
    asm volatile("ldmatrix.sync.aligned.m8n8.x2.shared.b16 {%0,%1}, [%2];"
        : "=r"(r[0]), "=r"(r[1]) : "r"(addr));
}
__device__ __forceinline__ void mma16816(float* c, const uint32_t* a, const uint32_t* b) {
    asm volatile(
        "mma.sync.aligned.m16n8k16.row.col.f32.bf16.bf16.f32 "
        "{%0,%1,%2,%3}, {%4,%5,%6,%7}, {%8,%9}, {%0,%1,%2,%3};"
        : "+f"(c[0]), "+f"(c[1]), "+f"(c[2]), "+f"(c[3])
        : "r"(a[0]), "r"(a[1]), "r"(a[2]), "r"(a[3]), "r"(b[0]), "r"(b[1]));
}
__device__ __forceinline__ uint32_t packbf(float x0, float x1) {
    uint32_t r;
    asm("cvt.rn.bf16x2.f32 %0, %1, %2;" : "=r"(r) : "f"(x1), "f"(x0));
    return r;
}
__device__ __forceinline__ void split_pair(float x0, float x1, uint32_t& hi, uint32_t& lo) {
    hi = packbf(x0, x1);
    float h0 = __bfloat162float(__float2bfloat16(x0));
    float h1 = __bfloat162float(__float2bfloat16(x1));
    lo = packbf(x0 - h0, x1 - h1);
}

// ======================= scratch ============================================
__device__ float  g_T0 [ROWS*NH];
__device__ __half g_T0h[ROWS*NH];
__device__ float  g_Tx1[ROWS*NH];
__device__ __half g_Tx1h[ROWS*NH];
__device__ float  g_Tx2[ROWS*NH];
__device__ float  g_cheb[ROWS*NH];

__device__ float g_deg[NN];
__device__ float g_dis[NN];
__device__ int   g_cnt[NN];
__device__ int   g_off[NN+1];
__device__ int   g_cur[NN];
__device__ int   g_csr_col[NE];
__device__ float g_csr_w[NE];
__device__ float g_Wcat[192*64];
__device__ float g_Wtc2[3*192*64];

// ======================= graph preprocessing ================================
__global__ void zero_kernel() {
    int i = blockIdx.x*256 + threadIdx.x;
    if (i < NN) { g_deg[i] = 0.f; g_cnt[i] = 0; g_cur[i] = 0; }
}
__global__ void degcnt_kernel(const int* __restrict__ ei, const float* __restrict__ ew) {
    int e = blockIdx.x*256 + threadIdx.x;
    if (e < NE) {
        int r = ei[e];
        atomicAdd(&g_deg[r], ew[e]);
        atomicAdd(&g_cnt[r], 1);
    }
}
__global__ void dis_kernel() {
    int i = blockIdx.x*256 + threadIdx.x;
    if (i < NN) {
        float d = g_deg[i];
        g_dis[i] = d > 0.f ? rsqrtf(d) : 0.f;
    }
}
__global__ void scan_kernel() {
    __shared__ int sums[1024];
    int tid = threadIdx.x;
    const int CH = (NN + 1023) / 1024;
    int base = tid * CH;
    int s = 0;
    for (int i = 0; i < CH; i++) { int idx = base + i; if (idx < NN) s += g_cnt[idx]; }
    sums[tid] = s;
    __syncthreads();
    for (int d = 1; d < 1024; d <<= 1) {
        int v = (tid >= d) ? sums[tid - d] : 0;
        __syncthreads();
        sums[tid] += v;
        __syncthreads();
    }
    int run = sums[tid] - s;
    for (int i = 0; i < CH; i++) {
        int idx = base + i;
        if (idx < NN) { g_off[idx] = run; run += g_cnt[idx]; }
    }
    if (tid == 1023) g_off[NN] = sums[1023];
}
__global__ void scatter_kernel(const int* __restrict__ ei, const float* __restrict__ ew) {
    int e = blockIdx.x*256 + threadIdx.x;
    if (e < NE) {
        int r = ei[e];
        int c = ei[NE + e];
        int pos = g_off[r] + atomicAdd(&g_cur[r], 1);
        g_csr_col[pos] = c;
        g_csr_w[pos]   = -g_dis[r] * ew[e] * g_dis[c];
    }
}

// ======================= weight repacking ===================================
__global__ void wcat_kernel(const float* __restrict__ W) {
    int idx = blockIdx.x*256 + threadIdx.x;
    if (idx >= 192*64) return;
    int k = idx >> 6, j = idx & 63;
    float v;
    if (k < 64)       v = W[k*64 + j] - W[2*4096 + k*64 + j];
    else if (k < 128) v = W[4096 + (k-64)*64 + j];
    else              v = 2.f * W[2*4096 + (k-128)*64 + j];
    g_Wcat[idx] = v;
}
__global__ void wtc2_kernel(const float* __restrict__ w1,
                            const float* __restrict__ w2,
                            const float* __restrict__ w3) {
    int idx = blockIdx.x*256 + threadIdx.x;
    if (idx >= 3*192*64) return;
    int j = idx / 12288;
    int r = idx - j*12288;
    int k = r >> 6, h = r & 63;
    int dt = k >> 6;
    int c  = k & 63;
    const float* w = (j == 0) ? w1 : (j == 1) ? w2 : w3;
    g_Wtc2[idx] = w[h*192 + c*3 + dt];
}

// ======================= TC1 (fp32 + fp16 shadow) ===========================
__global__ void tc1_kernel(const float* __restrict__ X,
                           const float* __restrict__ w1, const float* __restrict__ b1,
                           const float* __restrict__ w2, const float* __restrict__ b2,
                           const float* __restrict__ w3, const float* __restrict__ b3) {
    __shared__ float s1[384], s2[384], s3[384];
    __shared__ float sb[3][64];
    __shared__ float sx[4][8];
    int tid = threadIdx.x;
    for (int i = tid; i < 384; i += 256) { s1[i] = w1[i]; s2[i] = w2[i]; s3[i] = w3[i]; }
    if (tid < 64) { sb[0][tid] = b1[tid]; sb[1][tid] = b2[tid]; sb[2][tid] = b3[tid]; }
    int bt = blockIdx.y;
    int b = bt / NT, t = bt - b*NT;
    int n0 = blockIdx.x * 4;
    if (tid < 24) {
        int nl = tid / 6, idx = tid % 6;
        int k = idx >> 1, c = idx & 1;
        int tt = t + k - 1;
        float v = 0.f;
        if (tt >= 0 && tt < NT) v = X[(((b*NT + tt)*NN) + (n0 + nl))*NC + c];
        sx[nl][k*2 + c] = v;
    }
    __syncthreads();
    int h = tid & 63, nl = tid >> 6;
    float p = sb[0][h], q = sb[1][h], r = sb[2][h];
    #pragma unroll
    for (int k = 0; k < 3; k++)
        #pragma unroll
        for (int c = 0; c < 2; c++) {
            float xv = sx[nl][k*2 + c];
            int wi = h*6 + c*3 + k;
            p += s1[wi]*xv; q += s2[wi]*xv; r += s3[wi]*xv;
        }
    float sg = 1.f / (1.f + expf(-q));
    float o  = fmaxf(p*sg + r, 0.f);
    size_t idx = ((size_t)bt*NN + n0 + nl)*NH + h;
    g_T0[idx]  = o;
    g_T0h[idx] = __float2half(o);
}

// ======================= prop1: Tx1 = L T0 (fp16 gather) ====================
__global__ void prop1_kernel() {
    int n    = blockIdx.x;
    int warp = threadIdx.x >> 5, lane = threadIdx.x & 31;
    int bt   = blockIdx.y*8 + warp*2 + (lane >> 4);
    int hq   = lane & 15;
    int e0 = g_off[n], e1 = g_off[n+1];
    const uint2* xs = (const uint2*)g_T0h;
    float4 acc0 = make_float4(0.f, 0.f, 0.f, 0.f);
    float4 acc1 = make_float4(0.f, 0.f, 0.f, 0.f);
    int base = bt * NN;
    int e = e0;
    for (; e + 1 < e1; e += 2) {
        int   c0 = g_csr_col[e],   c1 = g_csr_col[e+1];
        float w0 = g_csr_w[e],     w1 = g_csr_w[e+1];
        uint2 u0 = __ldg(&xs[(base + c0)*16 + hq]);
        uint2 u1 = __ldg(&xs[(base + c1)*16 + hq]);
        float2 a01 = __half22float2(*(__half2*)&u0.x);
        float2 a23 = __half22float2(*(__half2*)&u0.y);
        float2 b01 = __half22float2(*(__half2*)&u1.x);
        float2 b23 = __half22float2(*(__half2*)&u1.y);
        acc0.x += w0*a01.x; acc0.y += w0*a01.y; acc0.z += w0*a23.x; acc0.w += w0*a23.y;
        acc1.x += w1*b01.x; acc1.y += w1*b01.y; acc1.z += w1*b23.x; acc1.w += w1*b23.y;
    }
    if (e < e1) {
        int   c = g_csr_col[e];
        float w = g_csr_w[e];
        uint2 u = __ldg(&xs[(base + c)*16 + hq]);
        float2 a01 = __half22float2(*(__half2*)&u.x);
        float2 a23 = __half22float2(*(__half2*)&u.y);
        acc0.x += w*a01.x; acc0.y += w*a01.y; acc0.z += w*a23.x; acc0.w += w*a23.y;
    }
    acc0.x += acc1.x; acc0.y += acc1.y; acc0.z += acc1.z; acc0.w += acc1.w;
    ((float4*)g_Tx1)[(base + n)*16 + hq] = acc0;
    __half2 h01 = __floats2half2_rn(acc0.x, acc0.y);
    __half2 h23 = __floats2half2_rn(acc0.z, acc0.w);
    uint2 hv;
    hv.x = *(uint32_t*)&h01;
    hv.y = *(uint32_t*)&h23;
    ((uint2*)g_Tx1h)[(base + n)*16 + hq] = hv;
}

// ======================= prop2: Tx2 = L Tx1 (fp16 gather) ===================
__global__ void prop2_kernel() {
    int n    = blockIdx.x;
    int warp = threadIdx.x >> 5, lane = threadIdx.x & 31;
    int bt   = blockIdx.y*8 + warp*2 + (lane >> 4);
    int hq   = lane & 15;
    int e0 = g_off[n], e1 = g_off[n+1];
    const uint2* xs = (const uint2*)g_Tx1h;
    float4 acc0 = make_float4(0.f, 0.f, 0.f, 0.f);
    float4 acc1 = make_float4(0.f, 0.f, 0.f, 0.f);
    int base = bt * NN;
    int e = e0;
    for (; e + 1 < e1; e += 2) {
        int   c0 = g_csr_col[e],   c1 = g_csr_col[e+1];
        float w0 = g_csr_w[e],     w1 = g_csr_w[e+1];
        uint2 u0 = __ldg(&xs[(base + c0)*16 + hq]);
        uint2 u1 = __ldg(&xs[(base + c1)*16 + hq]);
        float2 a01 = __half22float2(*(__half2*)&u0.x);
        float2 a23 = __half22float2(*(__half2*)&u0.y);
        float2 b01 = __half22float2(*(__half2*)&u1.x);
        float2 b23 = __half22float2(*(__half2*)&u1.y);
        acc0.x += w0*a01.x; acc0.y += w0*a01.y; acc0.z += w0*a23.x; acc0.w += w0*a23.y;
        acc1.x += w1*b01.x; acc1.y += w1*b01.y; acc1.z += w1*b23.x; acc1.w += w1*b23.y;
    }
    if (e < e1) {
        int   c = g_csr_col[e];
        float w = g_csr_w[e];
        uint2 u = __ldg(&xs[(base + c)*16 + hq]);
        float2 a01 = __half22float2(*(__half2*)&u.x);
        float2 a23 = __half22float2(*(__half2*)&u.y);
        acc0.x += w*a01.x; acc0.y += w*a01.y; acc0.z += w*a23.x; acc0.w += w*a23.y;
    }
    acc0.x += acc1.x; acc0.y += acc1.y; acc0.z += acc1.z; acc0.w += acc1.w;
    ((float4*)g_Tx2)[(base + n)*16 + hq] = acc0;
}

// ======================= cheb GEMM: persistent mma.sync bf16 hi/lo ==========
#define GC_AH   1024
#define GC_AL   19456
#define GC_BH   37888
#define GC_BL   65536
#define GC_SMEM 93184

__global__ __launch_bounds__(256) void gemm_cheb_mma(const float* __restrict__ cheb_b) {
    extern __shared__ char smem[];
    uint32_t sb = smem_to_u32(smem);
    int tid = threadIdx.x, warp = tid >> 5, lane = tid & 31;
    int warpM = warp >> 2, warpN = warp & 3;

    if (tid < 64) ((float*)smem)[tid] = cheb_b[tid];
    for (int p = tid; p < 6144; p += 256) {
        int n = p / 96;
        int kp = (p - n*96) * 2;
        int chunk = kp >> 6, kin = kp & 63;
        float w0 = g_Wcat[kp*64 + n];
        float w1 = g_Wcat[(kp+1)*64 + n];
        uint32_t hi, lo;
        split_pair(w0, w1, hi, lo);
        int off = (chunk*64 + n)*144 + kin*2;
        *(uint32_t*)(smem + GC_BH + off) = hi;
        *(uint32_t*)(smem + GC_BL + off) = lo;
    }
    __syncthreads();

    const float* bias = (const float*)smem;
    int ar = tid >> 1;
    int ac0 = (tid & 1) * 32;
    int g = lane >> 2, tg = lane & 3;

    for (int tile = blockIdx.x; tile < ROWS/128; tile += gridDim.x) {
        int row0 = tile*128;
        float acc[4][2][4];
        #pragma unroll
        for (int mt = 0; mt < 4; mt++)
            #pragma unroll
            for (int nt = 0; nt < 2; nt++)
                #pragma unroll
                for (int i = 0; i < 4; i++) acc[mt][nt][i] = 0.f;

        float4 pref[8];
        {
            const float4* pp = (const float4*)(g_T0 + ((size_t)(row0 + ar))*64 + ac0);
            #pragma unroll
            for (int i = 0; i < 8; i++) pref[i] = pp[i];
        }
        #pragma unroll
        for (int chunk = 0; chunk < 3; chunk++) {
            uint32_t* dh = (uint32_t*)(smem + GC_AH + ar*144 + ac0*2);
            uint32_t* dl = (uint32_t*)(smem + GC_AL + ar*144 + ac0*2);
            #pragma unroll
            for (int i = 0; i < 8; i++) {
                uint32_t h0, l0, h1, l1;
                split_pair(pref[i].x, pref[i].y, h0, l0);
                split_pair(pref[i].z, pref[i].w, h1, l1);
                dh[i*2] = h0; dh[i*2+1] = h1;
                dl[i*2] = l0; dl[i*2+1] = l1;
            }
            if (chunk < 2) {
                const float* src = (chunk == 0) ? g_Tx1 : g_Tx2;
                const float4* pp = (const float4*)(src + ((size_t)(row0 + ar))*64 + ac0);
                #pragma unroll
                for (int i = 0; i < 8; i++) pref[i] = pp[i];
            }
            __syncthreads();
            #pragma unroll
            for (int ks = 0; ks < 4; ks++) {
                int k0 = ks * 16;
                uint32_t ah[4][4], al[4][4];
                int arow = warpM*64 + ((lane>>3)&1)*8 + (lane&7);
                int acolb = (k0 + ((lane>>4)&1)*8) * 2;
                #pragma unroll
                for (int mt = 0; mt < 4; mt++) {
                    uint32_t ad = sb + GC_AH + (arow + mt*16)*144 + acolb;
                    ldsm4(ah[mt], ad);
                    ldsm4(al[mt], ad + (GC_AL - GC_AH));
                }
                int l4 = lane & 15;
                int brow = warpN*16 + (l4 & 7);
                int bcolb = (k0 + ((l4>>3)&1)*8) * 2;
                #pragma unroll
                for (int nt = 0; nt < 2; nt++) {
                    uint32_t bh[2], bl[2];
                    uint32_t bd = sb + GC_BH + (chunk*64 + brow + nt*8)*144 + bcolb;
                    ldsm2(bh, bd);
                    ldsm2(bl, bd + (GC_BL - GC_BH));
                    #pragma unroll
                    for (int mt = 0; mt < 4; mt++) {
                        mma16816(acc[mt][nt], ah[mt], bh);
                        mma16816(acc[mt][nt], ah[mt], bl);
                        mma16816(acc[mt][nt], al[mt], bh);
                    }
                }
            }
            __syncthreads();
        }
        #pragma unroll
        for (int mt = 0; mt < 4; mt++) {
            int row = row0 + warpM*64 + mt*16 + g;
            #pragma unroll
            for (int nt = 0; nt < 2; nt++) {
                int c = warpN*16 + nt*8 + tg*2;
                float2 v0 = make_float2(fmaxf(acc[mt][nt][0] + bias[c],   0.f),
                                        fmaxf(acc[mt][nt][1] + bias[c+1], 0.f));
                float2 v1 = make_float2(fmaxf(acc[mt][nt][2] + bias[c],   0.f),
                                        fmaxf(acc[mt][nt][3] + bias[c+1], 0.f));
                *(float2*)&g_cheb[(size_t)row*64 + c]     = v0;
                *(float2*)&g_cheb[(size_t)(row+8)*64 + c] = v1;
            }
        }
    }
}

// ======================= TC2: persistent mma.sync, gate-interleaved N =======
#define T2_AH   1024
#define T2_AL   19456
#define T2_BH   37888
#define T2_BL   120832
#define T2_SMEM 203776
#define NTILE_N 79
#define T2_TILES (BTT*NTILE_N)

__global__ __launch_bounds__(256) void tc2_mma(const float* __restrict__ b1,
                                               const float* __restrict__ b2,
                                               const float* __restrict__ b3,
                                               float* __restrict__ out) {
    extern __shared__ char smem[];
    uint32_t sb = smem_to_u32(smem);
    int tid = threadIdx.x, warp = tid >> 5, lane = tid & 31;
    int warpM = warp >> 2, warpN = warp & 3;

    if (tid < 64) {
        ((float*)smem)[tid]       = b1[tid];
        ((float*)smem)[64 + tid]  = b2[tid];
        ((float*)smem)[128 + tid] = b3[tid];
    }
    for (int p = tid; p < 18432; p += 256) {
        int n = p / 96;
        int kp = (p - n*96) * 2;
        int chunk = kp >> 6, kin = kp & 63;
        int gate = n >> 6, h = n & 63;
        float w0 = g_Wtc2[gate*12288 + kp*64 + h];
        float w1 = g_Wtc2[gate*12288 + (kp+1)*64 + h];
        uint32_t hi, lo;
        split_pair(w0, w1, hi, lo);
        int off = (chunk*192 + n)*144 + kin*2;
        *(uint32_t*)(smem + T2_BH + off) = hi;
        *(uint32_t*)(smem + T2_BL + off) = lo;
    }
    __syncthreads();

    const float* bP = (const float*)smem;
    const float* bQ = bP + 64;
    const float* bR = bP + 128;
    int ar = tid >> 1;
    int ac0 = (tid & 1) * 32;
    int g = lane >> 2, tg = lane & 3;

    for (int tt = blockIdx.x; tt < T2_TILES; tt += gridDim.x) {
        int bt = tt / NTILE_N, ntile = tt - bt*NTILE_N;
        int b = bt / NT, t = bt - b*NT;
        int an = ntile*128 + ar;

        float acc[4][6][4];
        #pragma unroll
        for (int mt = 0; mt < 4; mt++)
            #pragma unroll
            for (int nt = 0; nt < 6; nt++)
                #pragma unroll
                for (int i = 0; i < 4; i++) acc[mt][nt][i] = 0.f;

        const float4* pdt[3];
        #pragma unroll
        for (int dt = 0; dt < 3; dt++) {
            int ttm = t + dt - 1;
            pdt[dt] = ((an < NN) && ttm >= 0 && ttm < NT)
                    ? (const float4*)(g_cheb + ((size_t)((b*NT + ttm)*NN + an))*64 + ac0)
                    : (const float4*)0;
        }
        float4 pref[8];
        #pragma unroll
        for (int i = 0; i < 8; i++)
            pref[i] = pdt[0] ? pdt[0][i] : make_float4(0.f,0.f,0.f,0.f);

        #pragma unroll
        for (int chunk = 0; chunk < 3; chunk++) {
            uint32_t* dh = (uint32_t*)(smem + T2_AH + ar*144 + ac0*2);
            uint32_t* dl = (uint32_t*)(smem + T2_AL + ar*144 + ac0*2);
            #pragma unroll
            for (int i = 0; i < 8; i++) {
                uint32_t h0, l0, h1, l1;
                split_pair(pref[i].x, pref[i].y, h0, l0);
                split_pair(pref[i].z, pref[i].w, h1, l1);
                dh[i*2] = h0; dh[i*2+1] = h1;
                dl[i*2] = l0; dl[i*2+1] = l1;
            }
            if (chunk < 2) {
                const float4* pp = pdt[chunk+1];
                #pragma unroll
                for (int i = 0; i < 8; i++)
                    pref[i] = pp ? pp[i] : make_float4(0.f,0.f,0.f,0.f);
            }
            __syncthreads();
            #pragma unroll
            for (int ks = 0; ks < 4; ks++) {
                int k0 = ks * 16;
                uint32_t ah[4][4], al[4][4];
                int arow = warpM*64 + ((lane>>3)&1)*8 + (lane&7);
                int acolb = (k0 + ((lane>>4)&1)*8) * 2;
                #pragma unroll
                for (int mt = 0; mt < 4; mt++) {
                    uint32_t ad = sb + T2_AH + (arow + mt*16)*144 + acolb;
                    ldsm4(ah[mt], ad);
                    ldsm4(al[mt], ad + (T2_AL - T2_AH));
                }
                int l4 = lane & 15;
                int bcolb = (k0 + ((l4>>3)&1)*8) * 2;
                #pragma unroll
                for (int nt = 0; nt < 6; nt++) {
                    int gate = nt >> 1, j = nt & 1;
                    int brow = gate*64 + warpN*16 + j*8 + (l4 & 7);
                    uint32_t bh[2], bl[2];
                    uint32_t bd = sb + T2_BH + (chunk*192 + brow)*144 + bcolb;
                    ldsm2(bh, bd);
                    ldsm2(bl, bd + (T2_BL - T2_BH));
                    #pragma unroll
                    for (int mt = 0; mt < 4; mt++) {
                        mma16816(acc[mt][nt], ah[mt], bh);
                        mma16816(acc[mt][nt], ah[mt], bl);
                        mma16816(acc[mt][nt], al[mt], bh);
                    }
                }
            }
            __syncthreads();
        }
        #pragma unroll
        for (int mt = 0; mt < 4; mt++) {
            int n = ntile*128 + warpM*64 + mt*16 + g;
            #pragma unroll
            for (int j = 0; j < 2; j++) {
                int h = warpN*16 + j*8 + tg*2;
                float pb0 = bP[h], pb1 = bP[h+1];
                float qb0 = bQ[h], qb1 = bQ[h+1];
                float rb0 = bR[h], rb1 = bR[h+1];
                if (n < NN) {
                    float P0 = acc[mt][j][0] + pb0,   P1 = acc[mt][j][1] + pb1;
                    float Q0 = acc[mt][2+j][0] + qb0, Q1 = acc[mt][2+j][1] + qb1;
                    float R0 = acc[mt][4+j][0] + rb0, R1 = acc[mt][4+j][1] + rb1;
                    float s0 = 1.f / (1.f + expf(-Q0));
                    float s1 = 1.f / (1.f + expf(-Q1));
                    float2 o = make_float2(fmaxf(P0*s0 + R0, 0.f), fmaxf(P1*s1 + R1, 0.f));
                    *(float2*)&out[((size_t)bt*NN + n)*64 + h] = o;
                }
                if (n + 8 < NN) {
                    float P0 = acc[mt][j][2] + pb0,   P1 = acc[mt][j][3] + pb1;
                    float Q0 = acc[mt][2+j][2] + qb0, Q1 = acc[mt][2+j][3] + qb1;
                    float R0 = acc[mt][4+j][2] + rb0, R1 = acc[mt][4+j][3] + rb1;
                    float s0 = 1.f / (1.f + expf(-Q0));
                    float s1 = 1.f / (1.f + expf(-Q1));
                    float2 o = make_float2(fmaxf(P0*s0 + R0, 0.f), fmaxf(P1*s1 + R1, 0.f));
                    *(float2*)&out[((size_t)bt*NN + n + 8)*64 + h] = o;
                }
            }
        }
    }
}

// ======================= launcher ===========================================
extern "C" void kernel_launch(void* const* d_in, const int* in_sizes, int n_in,
                              void* d_out, int out_size) {
    const float* X     = (const float*)d_in[0];
    const int*   ei    = (const int*)  d_in[1];
    const float* ew    = (const float*)d_in[2];
    const float* t1w1  = (const float*)d_in[3];
    const float* t1b1  = (const float*)d_in[4];
    const float* t1w2  = (const float*)d_in[5];
    const float* t1b2  = (const float*)d_in[6];
    const float* t1w3  = (const float*)d_in[7];
    const float* t1b3  = (const float*)d_in[8];
    const float* chebW = (const float*)d_in[9];
    const float* chebB = (const float*)d_in[10];
    const float* t2w1  = (const float*)d_in[11];
    const float* t2b1  = (const float*)d_in[12];
    const float* t2w2  = (const float*)d_in[13];
    const float* t2b2  = (const float*)d_in[14];
    const float* t2w3  = (const float*)d_in[15];
    const float* t2b3  = (const float*)d_in[16];
    float* out = (float*)d_out;

    static int configured = 0;
    if (!configured) {
        cudaFuncSetAttribute(gemm_cheb_mma, cudaFuncAttributeMaxDynamicSharedMemorySize, GC_SMEM);
        cudaFuncSetAttribute(tc2_mma,       cudaFuncAttributeMaxDynamicSharedMemorySize, T2_SMEM);
        configured = 1;
    }

    zero_kernel   <<<(NN + 255)/256, 256>>>();
    degcnt_kernel <<<(NE + 255)/256, 256>>>(ei, ew);
    dis_kernel    <<<(NN + 255)/256, 256>>>();
    scan_kernel   <<<1, 1024>>>();
    scatter_kernel<<<(NE + 255)/256, 256>>>(ei, ew);

    wcat_kernel<<<(192*64 + 255)/256, 256>>>(chebW);
    wtc2_kernel<<<(3*192*64 + 255)/256, 256>>>(t2w1, t2w2, t2w3);

    tc1_kernel<<<dim3(NN/4, BTT), 256>>>(X, t1w1, t1b1, t1w2, t1b2, t1w3, t1b3);

    prop1_kernel<<<dim3(NN, 12), 128>>>();
    prop2_kernel<<<dim3(NN, 12), 128>>>();

    gemm_cheb_mma<<<296, 256, GC_SMEM>>>(chebB);

    tc2_mma<<<148, 256, T2_SMEM>>>(t2b1, t2b2, t2b3, out);
}

// round 13
// speedup vs baseline: 1.1786x; 1.0629x over previous
#include <cuda_runtime.h>
#include <cuda_bf16.h>
#include <cuda_fp16.h>
#include <math.h>
#include <stdint.h>

#define NB   8
#define NT   12
#define BTT  96
#define NN   10000
#define NH   64
#define NC   2
#define NE   320000
#define ROWS (BTT*NN)    // 960000

// ======================= mma.sync helpers ===================================
__device__ __forceinline__ uint32_t smem_to_u32(const void* p) {
    uint32_t a;
    asm("{ .reg .u64 t; cvta.to.shared.u64 t, %1; cvt.u32.u64 %0, t; }" : "=r"(a) : "l"(p));
    return a;
}
__device__ __forceinline__ void ldsm4(uint32_t* r, uint32_t addr) {
    asm volatile("ldmatrix.sync.aligned.m8n8.x4.shared.b16 {%0,%1,%2,%3}, [%4];"
        : "=r"(r[0]), "=r"(r[1]), "=r"(r[2]), "=r"(r[3]) : "r"(addr));
}
__device__ __forceinline__ void ldsm2(uint32_t* r, uint32_t addr) {
    asm volatile("ldmatrix.sync.aligned.m8n8.x2.shared.b16 {%0,%1}, [%2];"
        : "=r"(r[0]), "=r"(r[1]) : "r"(addr));
}
__device__ __forceinline__ void mma16816(float* c, const uint32_t* a, const uint32_t* b) {
    asm volatile(
        "mma.sync.aligned.m16n8k16.row.col.f32.bf16.bf16.f32 "
        "{%0,%1,%2,%3}, {%4,%5,%6,%7}, {%8,%9}, {%0,%1,%2,%3};"
        : "+f"(c[0]), "+f"(c[1]), "+f"(c[2]), "+f"(c[3])
        : "r"(a[0]), "r"(a[1]), "r"(a[2]), "r"(a[3]), "r"(b[0]), "r"(b[1]));
}
__device__ __forceinline__ uint32_t packbf(float x0, float x1) {
    uint32_t r;
    asm("cvt.rn.bf16x2.f32 %0, %1, %2;" : "=r"(r) : "f"(x1), "f"(x0));
    return r;
}
__device__ __forceinline__ void split_pair(float x0, float x1, uint32_t& hi, uint32_t& lo) {
    hi = packbf(x0, x1);
    float h0 = __bfloat162float(__float2bfloat16(x0));
    float h1 = __bfloat162float(__float2bfloat16(x1));
    lo = packbf(x0 - h0, x1 - h1);
}

// ======================= scratch ============================================
__device__ float  g_T0 [ROWS*NH];
__device__ __half g_T0h[ROWS*NH];
__device__ float  g_Tx1[ROWS*NH];
__device__ __half g_Tx1h[ROWS*NH];
__device__ float  g_Tx2[ROWS*NH];
__device__ float  g_cheb[ROWS*NH];

__device__ float g_deg[NN];
__device__ float g_dis[NN];
__device__ int   g_cnt[NN];
__device__ int   g_off[NN+1];
__device__ int   g_cur[NN];
__device__ int   g_csr_col[NE];
__device__ float g_csr_w[NE];
__device__ float g_Wcat[192*64];
__device__ float g_Wtc2[3*192*64];

// ======================= graph preprocessing ================================
__global__ void zero_kernel() {
    int i = blockIdx.x*256 + threadIdx.x;
    if (i < NN) { g_deg[i] = 0.f; g_cnt[i] = 0; g_cur[i] = 0; }
}
__global__ void degcnt_kernel(const int* __restrict__ ei, const float* __restrict__ ew) {
    int e = blockIdx.x*256 + threadIdx.x;
    if (e < NE) {
        int r = ei[e];
        atomicAdd(&g_deg[r], ew[e]);
        atomicAdd(&g_cnt[r], 1);
    }
}
__global__ void dis_kernel() {
    int i = blockIdx.x*256 + threadIdx.x;
    if (i < NN) {
        float d = g_deg[i];
        g_dis[i] = d > 0.f ? rsqrtf(d) : 0.f;
    }
}
__global__ void scan_kernel() {
    __shared__ int sums[1024];
    int tid = threadIdx.x;
    const int CH = (NN + 1023) / 1024;
    int base = tid * CH;
    int s = 0;
    for (int i = 0; i < CH; i++) { int idx = base + i; if (idx < NN) s += g_cnt[idx]; }
    sums[tid] = s;
    __syncthreads();
    for (int d = 1; d < 1024; d <<= 1) {
        int v = (tid >= d) ? sums[tid - d] : 0;
        __syncthreads();
        sums[tid] += v;
        __syncthreads();
    }
    int run = sums[tid] - s;
    for (int i = 0; i < CH; i++) {
        int idx = base + i;
        if (idx < NN) { g_off[idx] = run; run += g_cnt[idx]; }
    }
    if (tid == 1023) g_off[NN] = sums[1023];
}
__global__ void scatter_kernel(const int* __restrict__ ei, const float* __restrict__ ew) {
    int e = blockIdx.x*256 + threadIdx.x;
    if (e < NE) {
        int r = ei[e];
        int c = ei[NE + e];
        int pos = g_off[r] + atomicAdd(&g_cur[r], 1);
        g_csr_col[pos] = c;
        g_csr_w[pos]   = -g_dis[r] * ew[e] * g_dis[c];
    }
}

// ======================= weight repacking ===================================
__global__ void wcat_kernel(const float* __restrict__ W) {
    int idx = blockIdx.x*256 + threadIdx.x;
    if (idx >= 192*64) return;
    int k = idx >> 6, j = idx & 63;
    float v;
    if (k < 64)       v = W[k*64 + j] - W[2*4096 + k*64 + j];
    else if (k < 128) v = W[4096 + (k-64)*64 + j];
    else              v = 2.f * W[2*4096 + (k-128)*64 + j];
    g_Wcat[idx] = v;
}
__global__ void wtc2_kernel(const float* __restrict__ w1,
                            const float* __restrict__ w2,
                            const float* __restrict__ w3) {
    int idx = blockIdx.x*256 + threadIdx.x;
    if (idx >= 3*192*64) return;
    int j = idx / 12288;
    int r = idx - j*12288;
    int k = r >> 6, h = r & 63;
    int dt = k >> 6;
    int c  = k & 63;
    const float* w = (j == 0) ? w1 : (j == 1) ? w2 : w3;
    g_Wtc2[idx] = w[h*192 + c*3 + dt];
}

// ======================= TC1 (fp32 + fp16 shadow) ===========================
__global__ void tc1_kernel(const float* __restrict__ X,
                           const float* __restrict__ w1, const float* __restrict__ b1,
                           const float* __restrict__ w2, const float* __restrict__ b2,
                           const float* __restrict__ w3, const float* __restrict__ b3) {
    __shared__ float s1[384], s2[384], s3[384];
    __shared__ float sb[3][64];
    __shared__ float sx[4][8];
    int tid = threadIdx.x;
    for (int i = tid; i < 384; i += 256) { s1[i] = w1[i]; s2[i] = w2[i]; s3[i] = w3[i]; }
    if (tid < 64) { sb[0][tid] = b1[tid]; sb[1][tid] = b2[tid]; sb[2][tid] = b3[tid]; }
    int bt = blockIdx.y;
    int b = bt / NT, t = bt - b*NT;
    int n0 = blockIdx.x * 4;
    if (tid < 24) {
        int nl = tid / 6, idx = tid % 6;
        int k = idx >> 1, c = idx & 1;
        int tt = t + k - 1;
        float v = 0.f;
        if (tt >= 0 && tt < NT) v = X[(((b*NT + tt)*NN) + (n0 + nl))*NC + c];
        sx[nl][k*2 + c] = v;
    }
    __syncthreads();
    int h = tid & 63, nl = tid >> 6;
    float p = sb[0][h], q = sb[1][h], r = sb[2][h];
    #pragma unroll
    for (int k = 0; k < 3; k++)
        #pragma unroll
        for (int c = 0; c < 2; c++) {
            float xv = sx[nl][k*2 + c];
            int wi = h*6 + c*3 + k;
            p += s1[wi]*xv; q += s2[wi]*xv; r += s3[wi]*xv;
        }
    float sg = 1.f / (1.f + expf(-q));
    float o  = fmaxf(p*sg + r, 0.f);
    size_t idx = ((size_t)bt*NN + n0 + nl)*NH + h;
    g_T0[idx]  = o;
    g_T0h[idx] = __float2half(o);
}

// ======================= prop: smem-staged edges, 32 bt per block ===========
// block 256 thr = 16 btl x 16 hq, covers bt in [bt0, bt0+32) via 2 groups.
// Edge (col,w) staged to smem once per 256-edge chunk; gather fp16, acc fp32.
__device__ __forceinline__ void facc(float4& a, float w, uint2 u) {
    float2 p01 = __half22float2(*(__half2*)&u.x);
    float2 p23 = __half22float2(*(__half2*)&u.y);
    a.x += w*p01.x; a.y += w*p01.y; a.z += w*p23.x; a.w += w*p23.y;
}

__global__ __launch_bounds__(256) void prop_smem(const __half* __restrict__ srcH,
                                                 float* __restrict__ dstF,
                                                 __half* __restrict__ dstH) {
    __shared__ int   s_col[256];
    __shared__ float s_w[256];
    int n   = blockIdx.x;
    int bt0 = blockIdx.y * 32;
    int tid = threadIdx.x;
    int btl = tid >> 4, hq = tid & 15;
    int e0 = g_off[n], e1 = g_off[n+1];
    const uint2* xs = (const uint2*)srcH;
    float4 accA = make_float4(0.f,0.f,0.f,0.f);
    float4 accB = make_float4(0.f,0.f,0.f,0.f);
    int baseA = (bt0 + btl) * NN;
    int baseB = (bt0 + 16 + btl) * NN;

    for (int ce = e0; ce < e1; ce += 256) {
        int m = e1 - ce; if (m > 256) m = 256;
        __syncthreads();
        if (tid < m) {
            s_col[tid] = g_csr_col[ce + tid];
            s_w[tid]   = g_csr_w[ce + tid];
        }
        __syncthreads();
        int i = 0;
        for (; i + 1 < m; i += 2) {
            int   c0 = s_col[i],   c1 = s_col[i+1];
            float w0 = s_w[i],     w1 = s_w[i+1];
            uint2 uA0 = __ldg(&xs[(baseA + c0)*16 + hq]);
            uint2 uB0 = __ldg(&xs[(baseB + c0)*16 + hq]);
            uint2 uA1 = __ldg(&xs[(baseA + c1)*16 + hq]);
            uint2 uB1 = __ldg(&xs[(baseB + c1)*16 + hq]);
            facc(accA, w0, uA0); facc(accB, w0, uB0);
            facc(accA, w1, uA1); facc(accB, w1, uB1);
        }
        if (i < m) {
            int   c = s_col[i];
            float w = s_w[i];
            uint2 uA = __ldg(&xs[(baseA + c)*16 + hq]);
            uint2 uB = __ldg(&xs[(baseB + c)*16 + hq]);
            facc(accA, w, uA); facc(accB, w, uB);
        }
    }
    ((float4*)dstF)[(baseA + n)*16 + hq] = accA;
    ((float4*)dstF)[(baseB + n)*16 + hq] = accB;
    if (dstH) {
        __half2 a01 = __floats2half2_rn(accA.x, accA.y);
        __half2 a23 = __floats2half2_rn(accA.z, accA.w);
        __half2 b01 = __floats2half2_rn(accB.x, accB.y);
        __half2 b23 = __floats2half2_rn(accB.z, accB.w);
        uint2 ha, hb;
        ha.x = *(uint32_t*)&a01; ha.y = *(uint32_t*)&a23;
        hb.x = *(uint32_t*)&b01; hb.y = *(uint32_t*)&b23;
        ((uint2*)dstH)[(baseA + n)*16 + hq] = ha;
        ((uint2*)dstH)[(baseB + n)*16 + hq] = hb;
    }
}

// ======================= cheb GEMM: persistent mma.sync bf16 hi/lo ==========
#define GC_AH   1024
#define GC_AL   19456
#define GC_BH   37888
#define GC_BL   65536
#define GC_SMEM 93184

__global__ __launch_bounds__(256) void gemm_cheb_mma(const float* __restrict__ cheb_b) {
    extern __shared__ char smem[];
    uint32_t sb = smem_to_u32(smem);
    int tid = threadIdx.x, warp = tid >> 5, lane = tid & 31;
    int warpM = warp >> 2, warpN = warp & 3;

    if (tid < 64) ((float*)smem)[tid] = cheb_b[tid];
    for (int p = tid; p < 6144; p += 256) {
        int n = p / 96;
        int kp = (p - n*96) * 2;
        int chunk = kp >> 6, kin = kp & 63;
        float w0 = g_Wcat[kp*64 + n];
        float w1 = g_Wcat[(kp+1)*64 + n];
        uint32_t hi, lo;
        split_pair(w0, w1, hi, lo);
        int off = (chunk*64 + n)*144 + kin*2;
        *(uint32_t*)(smem + GC_BH + off) = hi;
        *(uint32_t*)(smem + GC_BL + off) = lo;
    }
    __syncthreads();

    const float* bias = (const float*)smem;
    int ar = tid >> 1;
    int ac0 = (tid & 1) * 32;
    int g = lane >> 2, tg = lane & 3;

    for (int tile = blockIdx.x; tile < ROWS/128; tile += gridDim.x) {
        int row0 = tile*128;
        float acc[4][2][4];
        #pragma unroll
        for (int mt = 0; mt < 4; mt++)
            #pragma unroll
            for (int nt = 0; nt < 2; nt++)
                #pragma unroll
                for (int i = 0; i < 4; i++) acc[mt][nt][i] = 0.f;

        float4 pref[8];
        {
            const float4* pp = (const float4*)(g_T0 + ((size_t)(row0 + ar))*64 + ac0);
            #pragma unroll
            for (int i = 0; i < 8; i++) pref[i] = pp[i];
        }
        #pragma unroll
        for (int chunk = 0; chunk < 3; chunk++) {
            uint32_t* dh = (uint32_t*)(smem + GC_AH + ar*144 + ac0*2);
            uint32_t* dl = (uint32_t*)(smem + GC_AL + ar*144 + ac0*2);
            #pragma unroll
            for (int i = 0; i < 8; i++) {
                uint32_t h0, l0, h1, l1;
                split_pair(pref[i].x, pref[i].y, h0, l0);
                split_pair(pref[i].z, pref[i].w, h1, l1);
                dh[i*2] = h0; dh[i*2+1] = h1;
                dl[i*2] = l0; dl[i*2+1] = l1;
            }
            if (chunk < 2) {
                const float* src = (chunk == 0) ? g_Tx1 : g_Tx2;
                const float4* pp = (const float4*)(src + ((size_t)(row0 + ar))*64 + ac0);
                #pragma unroll
                for (int i = 0; i < 8; i++) pref[i] = pp[i];
            }
            __syncthreads();
            #pragma unroll
            for (int ks = 0; ks < 4; ks++) {
                int k0 = ks * 16;
                uint32_t ah[4][4], al[4][4];
                int arow = warpM*64 + ((lane>>3)&1)*8 + (lane&7);
                int acolb = (k0 + ((lane>>4)&1)*8) * 2;
                #pragma unroll
                for (int mt = 0; mt < 4; mt++) {
                    uint32_t ad = sb + GC_AH + (arow + mt*16)*144 + acolb;
                    ldsm4(ah[mt], ad);
                    ldsm4(al[mt], ad + (GC_AL - GC_AH));
                }
                int l4 = lane & 15;
                int brow = warpN*16 + (l4 & 7);
                int bcolb = (k0 + ((l4>>3)&1)*8) * 2;
                #pragma unroll
                for (int nt = 0; nt < 2; nt++) {
                    uint32_t bh[2], bl[2];
                    uint32_t bd = sb + GC_BH + (chunk*64 + brow + nt*8)*144 + bcolb;
                    ldsm2(bh, bd);
                    ldsm2(bl, bd + (GC_BL - GC_BH));
                    #pragma unroll
                    for (int mt = 0; mt < 4; mt++) {
                        mma16816(acc[mt][nt], ah[mt], bh);
                        mma16816(acc[mt][nt], ah[mt], bl);
                        mma16816(acc[mt][nt], al[mt], bh);
                    }
                }
            }
            __syncthreads();
        }
        #pragma unroll
        for (int mt = 0; mt < 4; mt++) {
            int row = row0 + warpM*64 + mt*16 + g;
            #pragma unroll
            for (int nt = 0; nt < 2; nt++) {
                int c = warpN*16 + nt*8 + tg*2;
                float2 v0 = make_float2(fmaxf(acc[mt][nt][0] + bias[c],   0.f),
                                        fmaxf(acc[mt][nt][1] + bias[c+1], 0.f));
                float2 v1 = make_float2(fmaxf(acc[mt][nt][2] + bias[c],   0.f),
                                        fmaxf(acc[mt][nt][3] + bias[c+1], 0.f));
                *(float2*)&g_cheb[(size_t)row*64 + c]     = v0;
                *(float2*)&g_cheb[(size_t)(row+8)*64 + c] = v1;
            }
        }
    }
}

// ======================= TC2: persistent mma.sync, gate-interleaved N =======
#define T2_AH   1024
#define T2_AL   19456
#define T2_BH   37888
#define T2_BL   120832
#define T2_SMEM 203776
#define NTILE_N 79
#define T2_TILES (BTT*NTILE_N)

__global__ __launch_bounds__(256) void tc2_mma(const float* __restrict__ b1,
                                               const float* __restrict__ b2,
                                               const float* __restrict__ b3,
                                               float* __restrict__ out) {
    extern __shared__ char smem[];
    uint32_t sb = smem_to_u32(smem);
    int tid = threadIdx.x, warp = tid >> 5, lane = tid & 31;
    int warpM = warp >> 2, warpN = warp & 3;

    if (tid < 64) {
        ((float*)smem)[tid]       = b1[tid];
        ((float*)smem)[64 + tid]  = b2[tid];
        ((float*)smem)[128 + tid] = b3[tid];
    }
    for (int p = tid; p < 18432; p += 256) {
        int n = p / 96;
        int kp = (p - n*96) * 2;
        int chunk = kp >> 6, kin = kp & 63;
        int gate = n >> 6, h = n & 63;
        float w0 = g_Wtc2[gate*12288 + kp*64 + h];
        float w1 = g_Wtc2[gate*12288 + (kp+1)*64 + h];
        uint32_t hi, lo;
        split_pair(w0, w1, hi, lo);
        int off = (chunk*192 + n)*144 + kin*2;
        *(uint32_t*)(smem + T2_BH + off) = hi;
        *(uint32_t*)(smem + T2_BL + off) = lo;
    }
    __syncthreads();

    const float* bP = (const float*)smem;
    const float* bQ = bP + 64;
    const float* bR = bP + 128;
    int ar = tid >> 1;
    int ac0 = (tid & 1) * 32;
    int g = lane >> 2, tg = lane & 3;

    for (int tt = blockIdx.x; tt < T2_TILES; tt += gridDim.x) {
        int bt = tt / NTILE_N, ntile = tt - bt*NTILE_N;
        int b = bt / NT, t = bt - b*NT;
        int an = ntile*128 + ar;

        float acc[4][6][4];
        #pragma unroll
        for (int mt = 0; mt < 4; mt++)
            #pragma unroll
            for (int nt = 0; nt < 6; nt++)
                #pragma unroll
                for (int i = 0; i < 4; i++) acc[mt][nt][i] = 0.f;

        const float4* pdt[3];
        #pragma unroll
        for (int dt = 0; dt < 3; dt++) {
            int ttm = t + dt - 1;
            pdt[dt] = ((an < NN) && ttm >= 0 && ttm < NT)
                    ? (const float4*)(g_cheb + ((size_t)((b*NT + ttm)*NN + an))*64 + ac0)
                    : (const float4*)0;
        }
        float4 pref[8];
        #pragma unroll
        for (int i = 0; i < 8; i++)
            pref[i] = pdt[0] ? pdt[0][i] : make_float4(0.f,0.f,0.f,0.f);

        #pragma unroll
        for (int chunk = 0; chunk < 3; chunk++) {
            uint32_t* dh = (uint32_t*)(smem + T2_AH + ar*144 + ac0*2);
            uint32_t* dl = (uint32_t*)(smem + T2_AL + ar*144 + ac0*2);
            #pragma unroll
            for (int i = 0; i < 8; i++) {
                uint32_t h0, l0, h1, l1;
                split_pair(pref[i].x, pref[i].y, h0, l0);
                split_pair(pref[i].z, pref[i].w, h1, l1);
                dh[i*2] = h0; dh[i*2+1] = h1;
                dl[i*2] = l0; dl[i*2+1] = l1;
            }
            if (chunk < 2) {
                const float4* pp = pdt[chunk+1];
                #pragma unroll
                for (int i = 0; i < 8; i++)
                    pref[i] = pp ? pp[i] : make_float4(0.f,0.f,0.f,0.f);
            }
            __syncthreads();
            #pragma unroll
            for (int ks = 0; ks < 4; ks++) {
                int k0 = ks * 16;
                uint32_t ah[4][4], al[4][4];
                int arow = warpM*64 + ((lane>>3)&1)*8 + (lane&7);
                int acolb = (k0 + ((lane>>4)&1)*8) * 2;
                #pragma unroll
                for (int mt = 0; mt < 4; mt++) {
                    uint32_t ad = sb + T2_AH + (arow + mt*16)*144 + acolb;
                    ldsm4(ah[mt], ad);
                    ldsm4(al[mt], ad + (T2_AL - T2_AH));
                }
                int l4 = lane & 15;
                int bcolb = (k0 + ((l4>>3)&1)*8) * 2;
                #pragma unroll
                for (int nt = 0; nt < 6; nt++) {
                    int gate = nt >> 1, j = nt & 1;
                    int brow = gate*64 + warpN*16 + j*8 + (l4 & 7);
                    uint32_t bh[2], bl[2];
                    uint32_t bd = sb + T2_BH + (chunk*192 + brow)*144 + bcolb;
                    ldsm2(bh, bd);
                    ldsm2(bl, bd + (T2_BL - T2_BH));
                    #pragma unroll
                    for (int mt = 0; mt < 4; mt++) {
                        mma16816(acc[mt][nt], ah[mt], bh);
                        mma16816(acc[mt][nt], ah[mt], bl);
                        mma16816(acc[mt][nt], al[mt], bh);
                    }
                }
            }
            __syncthreads();
        }
        #pragma unroll
        for (int mt = 0; mt < 4; mt++) {
            int n = ntile*128 + warpM*64 + mt*16 + g;
            #pragma unroll
            for (int j = 0; j < 2; j++) {
                int h = warpN*16 + j*8 + tg*2;
                float pb0 = bP[h], pb1 = bP[h+1];
                float qb0 = bQ[h], qb1 = bQ[h+1];
                float rb0 = bR[h], rb1 = bR[h+1];
                if (n < NN) {
                    float P0 = acc[mt][j][0] + pb0,   P1 = acc[mt][j][1] + pb1;
                    float Q0 = acc[mt][2+j][0] + qb0, Q1 = acc[mt][2+j][1] + qb1;
                    float R0 = acc[mt][4+j][0] + rb0, R1 = acc[mt][4+j][1] + rb1;
                    float s0 = 1.f / (1.f + expf(-Q0));
                    float s1 = 1.f / (1.f + expf(-Q1));
                    float2 o = make_float2(fmaxf(P0*s0 + R0, 0.f), fmaxf(P1*s1 + R1, 0.f));
                    *(float2*)&out[((size_t)bt*NN + n)*64 + h] = o;
                }
                if (n + 8 < NN) {
                    float P0 = acc[mt][j][2] + pb0,   P1 = acc[mt][j][3] + pb1;
                    float Q0 = acc[mt][2+j][2] + qb0, Q1 = acc[mt][2+j][3] + qb1;
                    float R0 = acc[mt][4+j][2] + rb0, R1 = acc[mt][4+j][3] + rb1;
                    float s0 = 1.f / (1.f + expf(-Q0));
                    float s1 = 1.f / (1.f + expf(-Q1));
                    float2 o = make_float2(fmaxf(P0*s0 + R0, 0.f), fmaxf(P1*s1 + R1, 0.f));
                    *(float2*)&out[((size_t)bt*NN + n + 8)*64 + h] = o;
                }
            }
        }
    }
}

// ======================= launcher ===========================================
extern "C" void kernel_launch(void* const* d_in, const int* in_sizes, int n_in,
                              void* d_out, int out_size) {
    const float* X     = (const float*)d_in[0];
    const int*   ei    = (const int*)  d_in[1];
    const float* ew    = (const float*)d_in[2];
    const float* t1w1  = (const float*)d_in[3];
    const float* t1b1  = (const float*)d_in[4];
    const float* t1w2  = (const float*)d_in[5];
    const float* t1b2  = (const float*)d_in[6];
    const float* t1w3  = (const float*)d_in[7];
    const float* t1b3  = (const float*)d_in[8];
    const float* chebW = (const float*)d_in[9];
    const float* chebB = (const float*)d_in[10];
    const float* t2w1  = (const float*)d_in[11];
    const float* t2b1  = (const float*)d_in[12];
    const float* t2w2  = (const float*)d_in[13];
    const float* t2b2  = (const float*)d_in[14];
    const float* t2w3  = (const float*)d_in[15];
    const float* t2b3  = (const float*)d_in[16];
    float* out = (float*)d_out;

    static int configured = 0;
    if (!configured) {
        cudaFuncSetAttribute(gemm_cheb_mma, cudaFuncAttributeMaxDynamicSharedMemorySize, GC_SMEM);
        cudaFuncSetAttribute(tc2_mma,       cudaFuncAttributeMaxDynamicSharedMemorySize, T2_SMEM);
        configured = 1;
    }

    __half* T0h  = 0; cudaGetSymbolAddress((void**)&T0h,  g_T0h);
    __half* Tx1h = 0; cudaGetSymbolAddress((void**)&Tx1h, g_Tx1h);
    float*  Tx1  = 0; cudaGetSymbolAddress((void**)&Tx1,  g_Tx1);
    float*  Tx2  = 0; cudaGetSymbolAddress((void**)&Tx2,  g_Tx2);

    zero_kernel   <<<(NN + 255)/256, 256>>>();
    degcnt_kernel <<<(NE + 255)/256, 256>>>(ei, ew);
    dis_kernel    <<<(NN + 255)/256, 256>>>();
    scan_kernel   <<<1, 1024>>>();
    scatter_kernel<<<(NE + 255)/256, 256>>>(ei, ew);

    wcat_kernel<<<(192*64 + 255)/256, 256>>>(chebW);
    wtc2_kernel<<<(3*192*64 + 255)/256, 256>>>(t2w1, t2w2, t2w3);

    tc1_kernel<<<dim3(NN/4, BTT), 256>>>(X, t1w1, t1b1, t1w2, t1b2, t1w3, t1b3);

    prop_smem<<<dim3(NN, 3), 256>>>(T0h,  Tx1, Tx1h);
    prop_smem<<<dim3(NN, 3), 256>>>(Tx1h, Tx2, (__half*)0);

    gemm_cheb_mma<<<296, 256, GC_SMEM>>>(chebB);

    tc2_mma<<<148, 256, T2_SMEM>>>(t2b1, t2b2, t2b3, out);
}

// round 15
// speedup vs baseline: 1.3635x; 1.1569x over previous
#include <cuda_runtime.h>
#include <cuda_bf16.h>
#include <cuda_fp16.h>
#include <math.h>
#include <stdint.h>

#define NB   8
#define NT   12
#define BTT  96
#define NN   10000
#define NH   64
#define NC   2
#define NE   320000
#define ROWS (BTT*NN)    // 960000

// ======================= mma.sync helpers ===================================
__device__ __forceinline__ uint32_t smem_to_u32(const void* p) {
    uint32_t a;
    asm("{ .reg .u64 t; cvta.to.shared.u64 t, %1; cvt.u32.u64 %0, t; }" : "=r"(a) : "l"(p));
    return a;
}
__device__ __forceinline__ void ldsm4(uint32_t* r, uint32_t addr) {
    asm volatile("ldmatrix.sync.aligned.m8n8.x4.shared.b16 {%0,%1,%2,%3}, [%4];"
        : "=r"(r[0]), "=r"(r[1]), "=r"(r[2]), "=r"(r[3]) : "r"(addr));
}
__device__ __forceinline__ void ldsm2(uint32_t* r, uint32_t addr) {
    asm volatile("ldmatrix.sync.aligned.m8n8.x2.shared.b16 {%0,%1}, [%2];"
        : "=r"(r[0]), "=r"(r[1]) : "r"(addr));
}
__device__ __forceinline__ void mma16816(float* c, const uint32_t* a, const uint32_t* b) {
    asm volatile(
        "mma.sync.aligned.m16n8k16.row.col.f32.bf16.bf16.f32 "
        "{%0,%1,%2,%3}, {%4,%5,%6,%7}, {%8,%9}, {%0,%1,%2,%3};"
        : "+f"(c[0]), "+f"(c[1]), "+f"(c[2]), "+f"(c[3])
        : "r"(a[0]), "r"(a[1]), "r"(a[2]), "r"(a[3]), "r"(b[0]), "r"(b[1]));
}
__device__ __forceinline__ uint32_t packbf(float x0, float x1) {
    uint32_t r;
    asm("cvt.rn.bf16x2.f32 %0, %1, %2;" : "=r"(r) : "f"(x1), "f"(x0));
    return r;
}
__device__ __forceinline__ void split_pair(float x0, float x1, uint32_t& hi, uint32_t& lo) {
    hi = packbf(x0, x1);
    float h0 = __bfloat162float(__float2bfloat16(x0));
    float h1 = __bfloat162float(__float2bfloat16(x1));
    lo = packbf(x0 - h0, x1 - h1);
}
// split a packed half2 into bf16 hi/lo words (exact: fp16 -> bf16 + residual)
__device__ __forceinline__ void split_h2(uint32_t h2v, uint32_t& hi, uint32_t& lo) {
    float2 f = __half22float2(*(__half2*)&h2v);
    split_pair(f.x, f.y, hi, lo);
}

// ======================= scratch (fp16 intermediates only) ==================
__device__ __half g_T0h [ROWS*NH];
__device__ __half g_Tx1h[ROWS*NH];
__device__ __half g_Tx2h[ROWS*NH];
__device__ __half g_chebh[ROWS*NH];

__device__ float g_deg[NN];
__device__ float g_dis[NN];
__device__ int   g_cnt[NN];
__device__ int   g_off[NN+1];
__device__ int   g_cur[NN];
__device__ int   g_csr_col[NE];
__device__ float g_csr_w[NE];
__device__ float g_Wcat[192*64];
__device__ float g_Wtc2[3*192*64];

// ======================= graph preprocessing ================================
__global__ void zero_kernel() {
    int i = blockIdx.x*256 + threadIdx.x;
    if (i < NN) { g_deg[i] = 0.f; g_cnt[i] = 0; g_cur[i] = 0; }
}
__global__ void degcnt_kernel(const int* __restrict__ ei, const float* __restrict__ ew) {
    int e = blockIdx.x*256 + threadIdx.x;
    if (e < NE) {
        int r = ei[e];
        atomicAdd(&g_deg[r], ew[e]);
        atomicAdd(&g_cnt[r], 1);
    }
}
__global__ void dis_kernel() {
    int i = blockIdx.x*256 + threadIdx.x;
    if (i < NN) {
        float d = g_deg[i];
        g_dis[i] = d > 0.f ? rsqrtf(d) : 0.f;
    }
}
__global__ void scan_kernel() {
    __shared__ int sums[1024];
    int tid = threadIdx.x;
    const int CH = (NN + 1023) / 1024;
    int base = tid * CH;
    int s = 0;
    for (int i = 0; i < CH; i++) { int idx = base + i; if (idx < NN) s += g_cnt[idx]; }
    sums[tid] = s;
    __syncthreads();
    for (int d = 1; d < 1024; d <<= 1) {
        int v = (tid >= d) ? sums[tid - d] : 0;
        __syncthreads();
        sums[tid] += v;
        __syncthreads();
    }
    int run = sums[tid] - s;
    for (int i = 0; i < CH; i++) {
        int idx = base + i;
        if (idx < NN) { g_off[idx] = run; run += g_cnt[idx]; }
    }
    if (tid == 1023) g_off[NN] = sums[1023];
}
__global__ void scatter_kernel(const int* __restrict__ ei, const float* __restrict__ ew) {
    int e = blockIdx.x*256 + threadIdx.x;
    if (e < NE) {
        int r = ei[e];
        int c = ei[NE + e];
        int pos = g_off[r] + atomicAdd(&g_cur[r], 1);
        g_csr_col[pos] = c;
        g_csr_w[pos]   = -g_dis[r] * ew[e] * g_dis[c];
    }
}

// ======================= weight repacking ===================================
__global__ void wcat_kernel(const float* __restrict__ W) {
    int idx = blockIdx.x*256 + threadIdx.x;
    if (idx >= 192*64) return;
    int k = idx >> 6, j = idx & 63;
    float v;
    if (k < 64)       v = W[k*64 + j] - W[2*4096 + k*64 + j];
    else if (k < 128) v = W[4096 + (k-64)*64 + j];
    else              v = 2.f * W[2*4096 + (k-128)*64 + j];
    g_Wcat[idx] = v;
}
__global__ void wtc2_kernel(const float* __restrict__ w1,
                            const float* __restrict__ w2,
                            const float* __restrict__ w3) {
    int idx = blockIdx.x*256 + threadIdx.x;
    if (idx >= 3*192*64) return;
    int j = idx / 12288;
    int r = idx - j*12288;
    int k = r >> 6, h = r & 63;
    int dt = k >> 6;
    int c  = k & 63;
    const float* w = (j == 0) ? w1 : (j == 1) ? w2 : w3;
    g_Wtc2[idx] = w[h*192 + c*3 + dt];
}

// ======================= TC1 (fp16 out) =====================================
__global__ void tc1_kernel(const float* __restrict__ X,
                           const float* __restrict__ w1, const float* __restrict__ b1,
                           const float* __restrict__ w2, const float* __restrict__ b2,
                           const float* __restrict__ w3, const float* __restrict__ b3) {
    __shared__ float s1[384], s2[384], s3[384];
    __shared__ float sb[3][64];
    __shared__ float sx[4][8];
    int tid = threadIdx.x;
    for (int i = tid; i < 384; i += 256) { s1[i] = w1[i]; s2[i] = w2[i]; s3[i] = w3[i]; }
    if (tid < 64) { sb[0][tid] = b1[tid]; sb[1][tid] = b2[tid]; sb[2][tid] = b3[tid]; }
    int bt = blockIdx.y;
    int b = bt / NT, t = bt - b*NT;
    int n0 = blockIdx.x * 4;
    if (tid < 24) {
        int nl = tid / 6, idx = tid % 6;
        int k = idx >> 1, c = idx & 1;
        int tt = t + k - 1;
        float v = 0.f;
        if (tt >= 0 && tt < NT) v = X[(((b*NT + tt)*NN) + (n0 + nl))*NC + c];
        sx[nl][k*2 + c] = v;
    }
    __syncthreads();
    int h = tid & 63, nl = tid >> 6;
    float p = sb[0][h], q = sb[1][h], r = sb[2][h];
    #pragma unroll
    for (int k = 0; k < 3; k++)
        #pragma unroll
        for (int c = 0; c < 2; c++) {
            float xv = sx[nl][k*2 + c];
            int wi = h*6 + c*3 + k;
            p += s1[wi]*xv; q += s2[wi]*xv; r += s3[wi]*xv;
        }
    float sg = 1.f / (1.f + expf(-q));
    float o  = fmaxf(p*sg + r, 0.f);
    g_T0h[((size_t)bt*NN + n0 + nl)*NH + h] = __float2half(o);
}

// ======================= prop: smem-staged edges, 32 bt per block ===========
__device__ __forceinline__ void facc(float4& a, float w, uint2 u) {
    float2 p01 = __half22float2(*(__half2*)&u.x);
    float2 p23 = __half22float2(*(__half2*)&u.y);
    a.x += w*p01.x; a.y += w*p01.y; a.z += w*p23.x; a.w += w*p23.y;
}

__global__ __launch_bounds__(256) void prop_smem(const __half* __restrict__ srcH,
                                                 __half* __restrict__ dstH) {
    __shared__ int   s_col[256];
    __shared__ float s_w[256];
    int n   = blockIdx.x;
    int bt0 = blockIdx.y * 32;
    int tid = threadIdx.x;
    int btl = tid >> 4, hq = tid & 15;
    int e0 = g_off[n], e1 = g_off[n+1];
    const uint2* xs = (const uint2*)srcH;
    float4 accA = make_float4(0.f,0.f,0.f,0.f);
    float4 accB = make_float4(0.f,0.f,0.f,0.f);
    int baseA = (bt0 + btl) * NN;
    int baseB = (bt0 + 16 + btl) * NN;

    for (int ce = e0; ce < e1; ce += 256) {
        int m = e1 - ce; if (m > 256) m = 256;
        __syncthreads();
        if (tid < m) {
            s_col[tid] = g_csr_col[ce + tid];
            s_w[tid]   = g_csr_w[ce + tid];
        }
        __syncthreads();
        int i = 0;
        for (; i + 3 < m; i += 4) {
            int   c0 = s_col[i],   c1 = s_col[i+1], c2 = s_col[i+2], c3 = s_col[i+3];
            float w0 = s_w[i],     w1 = s_w[i+1],   w2 = s_w[i+2],   w3 = s_w[i+3];
            uint2 uA0 = __ldg(&xs[(baseA + c0)*16 + hq]);
            uint2 uB0 = __ldg(&xs[(baseB + c0)*16 + hq]);
            uint2 uA1 = __ldg(&xs[(baseA + c1)*16 + hq]);
            uint2 uB1 = __ldg(&xs[(baseB + c1)*16 + hq]);
            uint2 uA2 = __ldg(&xs[(baseA + c2)*16 + hq]);
            uint2 uB2 = __ldg(&xs[(baseB + c2)*16 + hq]);
            uint2 uA3 = __ldg(&xs[(baseA + c3)*16 + hq]);
            uint2 uB3 = __ldg(&xs[(baseB + c3)*16 + hq]);
            facc(accA, w0, uA0); facc(accB, w0, uB0);
            facc(accA, w1, uA1); facc(accB, w1, uB1);
            facc(accA, w2, uA2); facc(accB, w2, uB2);
            facc(accA, w3, uA3); facc(accB, w3, uB3);
        }
        for (; i < m; i++) {
            int   c = s_col[i];
            float w = s_w[i];
            uint2 uA = __ldg(&xs[(baseA + c)*16 + hq]);
            uint2 uB = __ldg(&xs[(baseB + c)*16 + hq]);
            facc(accA, w, uA); facc(accB, w, uB);
        }
    }
    __half2 a01 = __floats2half2_rn(accA.x, accA.y);
    __half2 a23 = __floats2half2_rn(accA.z, accA.w);
    __half2 b01 = __floats2half2_rn(accB.x, accB.y);
    __half2 b23 = __floats2half2_rn(accB.z, accB.w);
    uint2 ha, hb;
    ha.x = *(uint32_t*)&a01; ha.y = *(uint32_t*)&a23;
    hb.x = *(uint32_t*)&b01; hb.y = *(uint32_t*)&b23;
    ((uint2*)dstH)[(baseA + n)*16 + hq] = ha;
    ((uint2*)dstH)[(baseB + n)*16 + hq] = hb;
}

// ======================= cheb GEMM: persistent mma.sync bf16 hi/lo ==========
#define GC_AH   1024
#define GC_AL   19456
#define GC_BH   37888
#define GC_BL   65536
#define GC_SMEM 93184

__global__ __launch_bounds__(256) void gemm_cheb_mma(const float* __restrict__ cheb_b) {
    extern __shared__ char smem[];
    uint32_t sb = smem_to_u32(smem);
    int tid = threadIdx.x, warp = tid >> 5, lane = tid & 31;
    int warpM = warp >> 2, warpN = warp & 3;

    if (tid < 64) ((float*)smem)[tid] = cheb_b[tid];
    for (int p = tid; p < 6144; p += 256) {
        int n = p / 96;
        int kp = (p - n*96) * 2;
        int chunk = kp >> 6, kin = kp & 63;
        float w0 = g_Wcat[kp*64 + n];
        float w1 = g_Wcat[(kp+1)*64 + n];
        uint32_t hi, lo;
        split_pair(w0, w1, hi, lo);
        int off = (chunk*64 + n)*144 + kin*2;
        *(uint32_t*)(smem + GC_BH + off) = hi;
        *(uint32_t*)(smem + GC_BL + off) = lo;
    }
    __syncthreads();

    const float* bias = (const float*)smem;
    int ar = tid >> 1;
    int ac0 = (tid & 1) * 32;
    int g = lane >> 2, tg = lane & 3;

    for (int tile = blockIdx.x; tile < ROWS/128; tile += gridDim.x) {
        int row0 = tile*128;
        float acc[4][2][4];
        #pragma unroll
        for (int mt = 0; mt < 4; mt++)
            #pragma unroll
            for (int nt = 0; nt < 2; nt++)
                #pragma unroll
                for (int i = 0; i < 4; i++) acc[mt][nt][i] = 0.f;

        uint4 pref[4];
        {
            const uint4* pp = (const uint4*)(g_T0h + ((size_t)(row0 + ar))*64 + ac0);
            #pragma unroll
            for (int i = 0; i < 4; i++) pref[i] = pp[i];
        }
        #pragma unroll
        for (int chunk = 0; chunk < 3; chunk++) {
            uint32_t* dh = (uint32_t*)(smem + GC_AH + ar*144 + ac0*2);
            uint32_t* dl = (uint32_t*)(smem + GC_AL + ar*144 + ac0*2);
            #pragma unroll
            for (int i = 0; i < 4; i++) {
                split_h2(pref[i].x, dh[i*4+0], dl[i*4+0]);
                split_h2(pref[i].y, dh[i*4+1], dl[i*4+1]);
                split_h2(pref[i].z, dh[i*4+2], dl[i*4+2]);
                split_h2(pref[i].w, dh[i*4+3], dl[i*4+3]);
            }
            if (chunk < 2) {
                const __half* src = (chunk == 0) ? g_Tx1h : g_Tx2h;
                const uint4* pp = (const uint4*)(src + ((size_t)(row0 + ar))*64 + ac0);
                #pragma unroll
                for (int i = 0; i < 4; i++) pref[i] = pp[i];
            }
            __syncthreads();
            #pragma unroll
            for (int ks = 0; ks < 4; ks++) {
                int k0 = ks * 16;
                uint32_t ah[4][4], al[4][4];
                int arow = warpM*64 + ((lane>>3)&1)*8 + (lane&7);
                int acolb = (k0 + ((lane>>4)&1)*8) * 2;
                #pragma unroll
                for (int mt = 0; mt < 4; mt++) {
                    uint32_t ad = sb + GC_AH + (arow + mt*16)*144 + acolb;
                    ldsm4(ah[mt], ad);
                    ldsm4(al[mt], ad + (GC_AL - GC_AH));
                }
                int l4 = lane & 15;
                int brow = warpN*16 + (l4 & 7);
                int bcolb = (k0 + ((l4>>3)&1)*8) * 2;
                #pragma unroll
                for (int nt = 0; nt < 2; nt++) {
                    uint32_t bh[2], bl[2];
                    uint32_t bd = sb + GC_BH + (chunk*64 + brow + nt*8)*144 + bcolb;
                    ldsm2(bh, bd);
                    ldsm2(bl, bd + (GC_BL - GC_BH));
                    #pragma unroll
                    for (int mt = 0; mt < 4; mt++) {
                        mma16816(acc[mt][nt], ah[mt], bh);
                        mma16816(acc[mt][nt], ah[mt], bl);
                        mma16816(acc[mt][nt], al[mt], bh);
                    }
                }
            }
            __syncthreads();
        }
        #pragma unroll
        for (int mt = 0; mt < 4; mt++) {
            int row = row0 + warpM*64 + mt*16 + g;
            #pragma unroll
            for (int nt = 0; nt < 2; nt++) {
                int c = warpN*16 + nt*8 + tg*2;
                float v00 = fmaxf(acc[mt][nt][0] + bias[c],   0.f);
                float v01 = fmaxf(acc[mt][nt][1] + bias[c+1], 0.f);
                float v10 = fmaxf(acc[mt][nt][2] + bias[c],   0.f);
                float v11 = fmaxf(acc[mt][nt][3] + bias[c+1], 0.f);
                __half2 h0 = __floats2half2_rn(v00, v01);
                __half2 h1 = __floats2half2_rn(v10, v11);
                *(uint32_t*)&g_chebh[(size_t)row*64 + c]     = *(uint32_t*)&h0;
                *(uint32_t*)&g_chebh[(size_t)(row+8)*64 + c] = *(uint32_t*)&h1;
            }
        }
    }
}

// ======================= TC2: persistent mma.sync, gate-interleaved N =======
#define T2_AH   1024
#define T2_AL   19456
#define T2_BH   37888
#define T2_BL   120832
#define T2_SMEM 203776
#define NTILE_N 79
#define T2_TILES (BTT*NTILE_N)

__global__ __launch_bounds__(256) void tc2_mma(const float* __restrict__ b1,
                                               const float* __restrict__ b2,
                                               const float* __restrict__ b3,
                                               float* __restrict__ out) {
    extern __shared__ char smem[];
    uint32_t sb = smem_to_u32(smem);
    int tid = threadIdx.x, warp = tid >> 5, lane = tid & 31;
    int warpM = warp >> 2, warpN = warp & 3;

    if (tid < 64) {
        ((float*)smem)[tid]       = b1[tid];
        ((float*)smem)[64 + tid]  = b2[tid];
        ((float*)smem)[128 + tid] = b3[tid];
    }
    for (int p = tid; p < 18432; p += 256) {
        int n = p / 96;
        int kp = (p - n*96) * 2;
        int chunk = kp >> 6, kin = kp & 63;
        int gate = n >> 6, h = n & 63;
        float w0 = g_Wtc2[gate*12288 + kp*64 + h];
        float w1 = g_Wtc2[gate*12288 + (kp+1)*64 + h];
        uint32_t hi, lo;
        split_pair(w0, w1, hi, lo);
        int off = (chunk*192 + n)*144 + kin*2;
        *(uint32_t*)(smem + T2_BH + off) = hi;
        *(uint32_t*)(smem + T2_BL + off) = lo;
    }
    __syncthreads();

    const float* bP = (const float*)smem;
    const float* bQ = bP + 64;
    const float* bR = bP + 128;
    int ar = tid >> 1;
    int ac0 = (tid & 1) * 32;
    int g = lane >> 2, tg = lane & 3;

    for (int tt = blockIdx.x; tt < T2_TILES; tt += gridDim.x) {
        int bt = tt / NTILE_N, ntile = tt - bt*NTILE_N;
        int b = bt / NT, t = bt - b*NT;
        int an = ntile*128 + ar;

        float acc[4][6][4];
        #pragma unroll
        for (int mt = 0; mt < 4; mt++)
            #pragma unroll
            for (int nt = 0; nt < 6; nt++)
                #pragma unroll
                for (int i = 0; i < 4; i++) acc[mt][nt][i] = 0.f;

        const uint4* pdt[3];
        #pragma unroll
        for (int dt = 0; dt < 3; dt++) {
            int ttm = t + dt - 1;
            pdt[dt] = ((an < NN) && ttm >= 0 && ttm < NT)
                    ? (const uint4*)(g_chebh + ((size_t)((b*NT + ttm)*NN + an))*64 + ac0)
                    : (const uint4*)0;
        }
        uint4 zero4; zero4.x = zero4.y = zero4.z = zero4.w = 0;
        uint4 pref[4];
        #pragma unroll
        for (int i = 0; i < 4; i++)
            pref[i] = pdt[0] ? pdt[0][i] : zero4;

        #pragma unroll
        for (int chunk = 0; chunk < 3; chunk++) {
            uint32_t* dh = (uint32_t*)(smem + T2_AH + ar*144 + ac0*2);
            uint32_t* dl = (uint32_t*)(smem + T2_AL + ar*144 + ac0*2);
            #pragma unroll
            for (int i = 0; i < 4; i++) {
                split_h2(pref[i].x, dh[i*4+0], dl[i*4+0]);
                split_h2(pref[i].y, dh[i*4+1], dl[i*4+1]);
                split_h2(pref[i].z, dh[i*4+2], dl[i*4+2]);
                split_h2(pref[i].w, dh[i*4+3], dl[i*4+3]);
            }
            if (chunk < 2) {
                const uint4* pp = pdt[chunk+1];
                #pragma unroll
                for (int i = 0; i < 4; i++)
                    pref[i] = pp ? pp[i] : zero4;
            }
            __syncthreads();
            #pragma unroll
            for (int ks = 0; ks < 4; ks++) {
                int k0 = ks * 16;
                uint32_t ah[4][4], al[4][4];
                int arow = warpM*64 + ((lane>>3)&1)*8 + (lane&7);
                int acolb = (k0 + ((lane>>4)&1)*8) * 2;
                #pragma unroll
                for (int mt = 0; mt < 4; mt++) {
                    uint32_t ad = sb + T2_AH + (arow + mt*16)*144 + acolb;
                    ldsm4(ah[mt], ad);
                    ldsm4(al[mt], ad + (T2_AL - T2_AH));
                }
                int l4 = lane & 15;
                int bcolb = (k0 + ((l4>>3)&1)*8) * 2;
                #pragma unroll
                for (int nt = 0; nt < 6; nt++) {
                    int gate = nt >> 1, j = nt & 1;
                    int brow = gate*64 + warpN*16 + j*8 + (l4 & 7);
                    uint32_t bh[2], bl[2];
                    uint32_t bd = sb + T2_BH + (chunk*192 + brow)*144 + bcolb;
                    ldsm2(bh, bd);
                    ldsm2(bl, bd + (T2_BL - T2_BH));
                    #pragma unroll
                    for (int mt = 0; mt < 4; mt++) {
                        mma16816(acc[mt][nt], ah[mt], bh);
                        mma16816(acc[mt][nt], ah[mt], bl);
                        mma16816(acc[mt][nt], al[mt], bh);
                    }
                }
            }
            __syncthreads();
        }
        #pragma unroll
        for (int mt = 0; mt < 4; mt++) {
            int n = ntile*128 + warpM*64 + mt*16 + g;
            #pragma unroll
            for (int j = 0; j < 2; j++) {
                int h = warpN*16 + j*8 + tg*2;
                float pb0 = bP[h], pb1 = bP[h+1];
                float qb0 = bQ[h], qb1 = bQ[h+1];
                float rb0 = bR[h], rb1 = bR[h+1];
                if (n < NN) {
                    float P0 = acc[mt][j][0] + pb0,   P1 = acc[mt][j][1] + pb1;
                    float Q0 = acc[mt][2+j][0] + qb0, Q1 = acc[mt][2+j][1] + qb1;
                    float R0 = acc[mt][4+j][0] + rb0, R1 = acc[mt][4+j][1] + rb1;
                    float s0 = 1.f / (1.f + expf(-Q0));
                    float s1 = 1.f / (1.f + expf(-Q1));
                    float2 o = make_float2(fmaxf(P0*s0 + R0, 0.f), fmaxf(P1*s1 + R1, 0.f));
                    *(float2*)&out[((size_t)bt*NN + n)*64 + h] = o;
                }
                if (n + 8 < NN) {
                    float P0 = acc[mt][j][2] + pb0,   P1 = acc[mt][j][3] + pb1;
                    float Q0 = acc[mt][2+j][2] + qb0, Q1 = acc[mt][2+j][3] + qb1;
                    float R0 = acc[mt][4+j][2] + rb0, R1 = acc[mt][4+j][3] + rb1;
                    float s0 = 1.f / (1.f + expf(-Q0));
                    float s1 = 1.f / (1.f + expf(-Q1));
                    float2 o = make_float2(fmaxf(P0*s0 + R0, 0.f), fmaxf(P1*s1 + R1, 0.f));
                    *(float2*)&out[((size_t)bt*NN + n + 8)*64 + h] = o;
                }
            }
        }
    }
}

// ======================= launcher ===========================================
extern "C" void kernel_launch(void* const* d_in, const int* in_sizes, int n_in,
                              void* d_out, int out_size) {
    const float* X     = (const float*)d_in[0];
    const int*   ei    = (const int*)  d_in[1];
    const float* ew    = (const float*)d_in[2];
    const float* t1w1  = (const float*)d_in[3];
    const float* t1b1  = (const float*)d_in[4];
    const float* t1w2  = (const float*)d_in[5];
    const float* t1b2  = (const float*)d_in[6];
    const float* t1w3  = (const float*)d_in[7];
    const float* t1b3  = (const float*)d_in[8];
    const float* chebW = (const float*)d_in[9];
    const float* chebB = (const float*)d_in[10];
    const float* t2w1  = (const float*)d_in[11];
    const float* t2b1  = (const float*)d_in[12];
    const float* t2w2  = (const float*)d_in[13];
    const float* t2b2  = (const float*)d_in[14];
    const float* t2w3  = (const float*)d_in[15];
    const float* t2b3  = (const float*)d_in[16];
    float* out = (float*)d_out;

    static int configured = 0;
    if (!configured) {
        cudaFuncSetAttribute(gemm_cheb_mma, cudaFuncAttributeMaxDynamicSharedMemorySize, GC_SMEM);
        cudaFuncSetAttribute(tc2_mma,       cudaFuncAttributeMaxDynamicSharedMemorySize, T2_SMEM);
        configured = 1;
    }

    __half* T0h  = 0; cudaGetSymbolAddress((void**)&T0h,  g_T0h);
    __half* Tx1h = 0; cudaGetSymbolAddress((void**)&Tx1h, g_Tx1h);
    __half* Tx2h = 0; cudaGetSymbolAddress((void**)&Tx2h, g_Tx2h);

    zero_kernel   <<<(NN + 255)/256, 256>>>();
    degcnt_kernel <<<(NE + 255)/256, 256>>>(ei, ew);
    dis_kernel    <<<(NN + 255)/256, 256>>>();
    scan_kernel   <<<1, 1024>>>();
    scatter_kernel<<<(NE + 255)/256, 256>>>(ei, ew);

    wcat_kernel<<<(192*64 + 255)/256, 256>>>(chebW);
    wtc2_kernel<<<(3*192*64 + 255)/256, 256>>>(t2w1, t2w2, t2w3);

    tc1_kernel<<<dim3(NN/4, BTT), 256>>>(X, t1w1, t1b1, t1w2, t1b2, t1w3, t1b3);

    prop_smem<<<dim3(NN, 3), 256>>>(T0h,  Tx1h);
    prop_smem<<<dim3(NN, 3), 256>>>(Tx1h, Tx2h);

    gemm_cheb_mma<<<296, 256, GC_SMEM>>>(chebB);

    tc2_mma<<<148, 256, T2_SMEM>>>(t2b1, t2b2, t2b3, out);
}